// round 7
// baseline (speedup 1.0000x reference)
#include <cuda_runtime.h>
#include <math.h>

#define B_SZ 64
#define S_SZ 1024
#define I_SZ 512
#define H_SZ 512

// ---------------- static device scratch (no allocations allowed) ----------------
__device__ float g_xg  [(size_t)S_SZ * 3 * B_SZ * H_SZ];  // [S][3][B][H]
__device__ float g_ys0 [(size_t)S_SZ * B_SZ * H_SZ];      // layer-0 fwd outputs [S][B][H]
__device__ float g_ys1 [(size_t)S_SZ * B_SZ * H_SZ];      // layer-1 fwd outputs
__device__ float g_hb0 [B_SZ * H_SZ];
__device__ float g_hb1 [B_SZ * H_SZ];
__device__ float g_wpk0[3 * 512 * 512];                   // packed Wh layer0: [g][k/4][col][4]
__device__ float g_wpk1[3 * 512 * 512];                   // packed Wh layer1

// ---------------- tf32 helpers ----------------
__device__ __forceinline__ unsigned f2tf(float x) {
    unsigned u;
    asm("cvt.rna.tf32.f32 %0, %1;" : "=r"(u) : "f"(x));
    return u;
}

__device__ __forceinline__ void mma8(float* c, const unsigned* a, unsigned b0, unsigned b1) {
    asm volatile(
        "mma.sync.aligned.m16n8k8.row.col.f32.tf32.tf32.f32 "
        "{%0,%1,%2,%3}, {%4,%5,%6,%7}, {%8,%9}, {%0,%1,%2,%3};"
        : "+f"(c[0]), "+f"(c[1]), "+f"(c[2]), "+f"(c[3])
        : "r"(a[0]), "r"(a[1]), "r"(a[2]), "r"(a[3]), "r"(b0), "r"(b1));
}

__device__ __forceinline__ float f4get(const float4& v, int e) {
    return e == 0 ? v.x : (e == 1 ? v.y : (e == 2 ? v.z : v.w));
}

// ---------------- projection GEMM (verified working, unchanged) ----------------
__global__ void __launch_bounds__(256) proj_kernel(
    const float* __restrict__ X, long sb, long ss,
    const float* __restrict__ W, const float* __restrict__ bias,
    float* __restrict__ out, int Srows)
{
    __shared__ float As[128][36];
    __shared__ float Bs[32][136];

    const int M  = Srows * B_SZ;
    const int m0 = blockIdx.y * 128;
    const int n0 = blockIdx.x * 128;
    const int g  = n0 >> 9;
    const int h0 = n0 & 511;
    const float* Wg = W + (size_t)g * H_SZ * H_SZ;

    const int tid  = threadIdx.x;
    const int lane = tid & 31;
    const int warp = tid >> 5;
    const int wm   = warp & 3;
    const int wn   = warp >> 2;

    float acc[2][8][4];
#pragma unroll
    for (int i = 0; i < 2; i++)
#pragma unroll
        for (int jf = 0; jf < 8; jf++)
#pragma unroll
            for (int k = 0; k < 4; k++) acc[i][jf][k] = 0.f;

    for (int k0 = 0; k0 < H_SZ; k0 += 32) {
#pragma unroll
        for (int i = 0; i < 4; i++) {
            int idx = tid + i * 256;
            int row = idx >> 3;
            int kk  = (idx & 7) << 2;
            float4 v = make_float4(0.f, 0.f, 0.f, 0.f);
            int r = m0 + row;
            if (r < M) {
                int s = r >> 6, b = r & 63;
                v = *(const float4*)(X + (size_t)b * sb + (size_t)s * ss + k0 + kk);
            }
            As[row][kk + 0] = __uint_as_float(f2tf(v.x));
            As[row][kk + 1] = __uint_as_float(f2tf(v.y));
            As[row][kk + 2] = __uint_as_float(f2tf(v.z));
            As[row][kk + 3] = __uint_as_float(f2tf(v.w));
        }
#pragma unroll
        for (int i = 0; i < 4; i++) {
            int idx = tid + i * 256;
            int kk  = idx >> 5;
            int nn  = (idx & 31) << 2;
            float4 v = *(const float4*)(Wg + (size_t)(k0 + kk) * H_SZ + h0 + nn);
            Bs[kk][nn + 0] = __uint_as_float(f2tf(v.x));
            Bs[kk][nn + 1] = __uint_as_float(f2tf(v.y));
            Bs[kk][nn + 2] = __uint_as_float(f2tf(v.z));
            Bs[kk][nn + 3] = __uint_as_float(f2tf(v.w));
        }
        __syncthreads();

#pragma unroll
        for (int kq = 0; kq < 4; kq++) {
            const int kr = kq * 8;
            unsigned a[2][4];
#pragma unroll
            for (int mf = 0; mf < 2; mf++) {
                int rb = wm * 32 + mf * 16 + (lane >> 2);
                int c  = kr + (lane & 3);
                a[mf][0] = __float_as_uint(As[rb][c]);
                a[mf][1] = __float_as_uint(As[rb + 8][c]);
                a[mf][2] = __float_as_uint(As[rb][c + 4]);
                a[mf][3] = __float_as_uint(As[rb + 8][c + 4]);
            }
#pragma unroll
            for (int nf = 0; nf < 8; nf++) {
                int cb = wn * 64 + nf * 8 + (lane >> 2);
                unsigned b0 = __float_as_uint(Bs[kr + (lane & 3)][cb]);
                unsigned b1 = __float_as_uint(Bs[kr + (lane & 3) + 4][cb]);
                mma8(acc[0][nf], a[0], b0, b1);
                mma8(acc[1][nf], a[1], b0, b1);
            }
        }
        __syncthreads();
    }

#pragma unroll
    for (int mf = 0; mf < 2; mf++) {
#pragma unroll
        for (int nf = 0; nf < 8; nf++) {
            int col = wn * 64 + nf * 8 + ((lane & 3) << 1);
            int h   = h0 + col;
            float b0v = bias[g * H_SZ + h];
            float b1v = bias[g * H_SZ + h + 1];
            int r = m0 + wm * 32 + mf * 16 + (lane >> 2);
            if (r < M) {
                int s = r >> 6, b = r & 63;
                float* o = out + ((size_t)(s * 3 + g) * B_SZ + b) * H_SZ + h;
                o[0] = acc[mf][nf][0] + b0v;
                o[1] = acc[mf][nf][1] + b1v;
            }
            int r2 = r + 8;
            if (r2 < M) {
                int s = r2 >> 6, b = r2 & 63;
                float* o = out + ((size_t)(s * 3 + g) * B_SZ + b) * H_SZ + h;
                o[0] = acc[mf][nf][2] + b0v;
                o[1] = acc[mf][nf][3] + b1v;
            }
        }
    }
}

// ---------------- Wh pre-pack: [g][k][col] -> [g][k/4][col][k%4] ----------------
__global__ void __launch_bounds__(256) pack_wh(const float* __restrict__ Wh,
                                               float* __restrict__ wpk)
{
    int idx = blockIdx.x * 256 + threadIdx.x;
    if (idx < 3 * 512 * 512) {
        int col = idx & 511;
        int k   = (idx >> 9) & 511;
        int g   = idx >> 18;
        wpk[((((size_t)g * 128 + (k >> 2)) * 512 + col) << 2) + (k & 3)] = Wh[idx];
    }
}

// ---------------- recurrent scan: HW clusters, f32x2 FMA, smem weight cache ----------------
// grid (8, 16): x = colgroup (64 cols), y = bgrp (4 batches). Cluster = 8 CTAs along x.
// Per CTA: 64 cols x 3 gates x 4 batches x K=512. Thread: kc = tid>>6 (64 k), cl = tid&63.
// Accumulators are f32x2 batch-pairs (b0,b1)/(b2,b3); h staged transposed hs[k][b].
// Weight cache: t-granules 0..6 of each kc (7/16 of K) resident in smem, rest streamed from L2.
#define WC_T       7
#define WC_FLOAT4  (8 * WC_T * 3 * 64)                     // 10752 float4 = 172032 B
#define SCAN_SMEM_BYTES ((2048 + 6144) * 4 + WC_FLOAT4 * 16)  // hs 8KB + red 24KB + wc 168KB = 204800

__global__ void __launch_bounds__(512, 1) __cluster_dims__(8, 1, 1)
scan_kernel(const float* __restrict__ xg,    // [S][3][B][H]
            const float4* __restrict__ wpk,  // [3][128][512] float4 (packed)
            float* __restrict__ ys,          // [S][B][H]
            int S)
{
    extern __shared__ float sm[];
    float*  hs  = sm;                        // [512 k][4 b] = 2048 floats
    float*  red = sm + 2048;                 // [8 kc][3 g][4 b][64 cl] = 6144 floats
    float4* wc4 = (float4*)(sm + 2048 + 6144);

    const int tid = threadIdx.x;
    const int kc  = tid >> 6;                // 0..7  (64 k each)
    const int cl  = tid & 63;                // 0..63 col-local
    const int j0  = blockIdx.x << 6;
    const int b0  = blockIdx.y << 2;
    const int col = j0 + cl;
    const int k4b = kc << 4;

    // one-time weight cache fill: wc4[(kc*21 + t*3 + g)*64 + cl] = wpk[g][kc*16+t][j0+cl]
    for (int i = tid; i < WC_FLOAT4; i += 512) {
        int ccl = i & 63;
        int r   = i >> 6;        // kc*21 + t*3 + g
        int g   = r % 3;
        int r2  = r / 3;
        int t   = r2 % WC_T;
        int kk  = r2 / WC_T;
        wc4[i] = wpk[((size_t)(g * 128 + kk * 16 + t) << 9) + j0 + ccl];
    }

    // gate-stage mapping (tid < 256): gb = batch-local, gj = col-local
    const int gb = tid >> 6;
    const int gj = tid & 63;

    for (int s = 0; s < S; s++) {
        // stage h_prev transposed: hs[k][b] (one float4 per k)
        {
            int k = tid;   // 0..511
            if (k < 512) {
                float4 hv;
                if (s == 0) {
                    hv = make_float4(0.f, 0.f, 0.f, 0.f);
                } else {
                    const float* yb = ys + (size_t)(s - 1) * (B_SZ * H_SZ)
                                         + (size_t)b0 * H_SZ + k;
                    hv.x = __ldcg(yb);
                    hv.y = __ldcg(yb + 512);
                    hv.z = __ldcg(yb + 1024);
                    hv.w = __ldcg(yb + 1536);
                }
                ((float4*)hs)[k] = hv;
            }
        }
        __syncthreads();

        unsigned long long a01[3] = {0ull, 0ull, 0ull};
        unsigned long long a23[3] = {0ull, 0ull, 0ull};

        // cached region: t in [0, WC_T)
#pragma unroll
        for (int t = 0; t < WC_T; t++) {
            const int base = (kc * 21 + t * 3) * 64 + cl;
            float4 w0v = wc4[base];
            float4 w1v = wc4[base + 64];
            float4 w2v = wc4[base + 128];
            const int k4 = k4b + t;
#pragma unroll
            for (int e = 0; e < 4; e++) {
                const ulonglong2 hp = *(const ulonglong2*)(hs + (((k4 << 2) + e) << 2));
                unsigned long long wd;
                unsigned wb;
                wb = __float_as_uint(f4get(w0v, e));
                asm("mov.b64 %0,{%1,%1};" : "=l"(wd) : "r"(wb));
                asm("fma.rn.f32x2 %0, %1, %2, %0;" : "+l"(a01[0]) : "l"(wd), "l"(hp.x));
                asm("fma.rn.f32x2 %0, %1, %2, %0;" : "+l"(a23[0]) : "l"(wd), "l"(hp.y));
                wb = __float_as_uint(f4get(w1v, e));
                asm("mov.b64 %0,{%1,%1};" : "=l"(wd) : "r"(wb));
                asm("fma.rn.f32x2 %0, %1, %2, %0;" : "+l"(a01[1]) : "l"(wd), "l"(hp.x));
                asm("fma.rn.f32x2 %0, %1, %2, %0;" : "+l"(a23[1]) : "l"(wd), "l"(hp.y));
                wb = __float_as_uint(f4get(w2v, e));
                asm("mov.b64 %0,{%1,%1};" : "=l"(wd) : "r"(wb));
                asm("fma.rn.f32x2 %0, %1, %2, %0;" : "+l"(a01[2]) : "l"(wd), "l"(hp.x));
                asm("fma.rn.f32x2 %0, %1, %2, %0;" : "+l"(a23[2]) : "l"(wd), "l"(hp.y));
            }
        }

        // streamed region: t in [WC_T, 16)
#pragma unroll 3
        for (int t = WC_T; t < 16; t++) {
            const int k4 = k4b + t;
            float4 w0v = __ldg(&wpk[((size_t)(0 * 128 + k4) << 9) + col]);
            float4 w1v = __ldg(&wpk[((size_t)(1 * 128 + k4) << 9) + col]);
            float4 w2v = __ldg(&wpk[((size_t)(2 * 128 + k4) << 9) + col]);
#pragma unroll
            for (int e = 0; e < 4; e++) {
                const ulonglong2 hp = *(const ulonglong2*)(hs + (((k4 << 2) + e) << 2));
                unsigned long long wd;
                unsigned wb;
                wb = __float_as_uint(f4get(w0v, e));
                asm("mov.b64 %0,{%1,%1};" : "=l"(wd) : "r"(wb));
                asm("fma.rn.f32x2 %0, %1, %2, %0;" : "+l"(a01[0]) : "l"(wd), "l"(hp.x));
                asm("fma.rn.f32x2 %0, %1, %2, %0;" : "+l"(a23[0]) : "l"(wd), "l"(hp.y));
                wb = __float_as_uint(f4get(w1v, e));
                asm("mov.b64 %0,{%1,%1};" : "=l"(wd) : "r"(wb));
                asm("fma.rn.f32x2 %0, %1, %2, %0;" : "+l"(a01[1]) : "l"(wd), "l"(hp.x));
                asm("fma.rn.f32x2 %0, %1, %2, %0;" : "+l"(a23[1]) : "l"(wd), "l"(hp.y));
                wb = __float_as_uint(f4get(w2v, e));
                asm("mov.b64 %0,{%1,%1};" : "=l"(wd) : "r"(wb));
                asm("fma.rn.f32x2 %0, %1, %2, %0;" : "+l"(a01[2]) : "l"(wd), "l"(hp.x));
                asm("fma.rn.f32x2 %0, %1, %2, %0;" : "+l"(a23[2]) : "l"(wd), "l"(hp.y));
            }
        }

        // unpack f32x2 accumulators into cross-kc reduction buffer
#pragma unroll
        for (int g = 0; g < 3; g++) {
            unsigned r0, r1;
            asm("mov.b64 {%0,%1}, %2;" : "=r"(r0), "=r"(r1) : "l"(a01[g]));
            red[((kc * 3 + g) * 4 + 0) * 64 + cl] = __uint_as_float(r0);
            red[((kc * 3 + g) * 4 + 1) * 64 + cl] = __uint_as_float(r1);
            asm("mov.b64 {%0,%1}, %2;" : "=r"(r0), "=r"(r1) : "l"(a23[g]));
            red[((kc * 3 + g) * 4 + 2) * 64 + cl] = __uint_as_float(r0);
            red[((kc * 3 + g) * 4 + 3) * 64 + cl] = __uint_as_float(r1);
        }
        __syncthreads();

        // gate stage: 256 threads, one per (batch gb, col gj)
        if (tid < 256) {
            float a0 = 0.f, a1 = 0.f, a2 = 0.f;
#pragma unroll
            for (int c = 0; c < 8; c++) {
                a0 += red[((c * 3 + 0) * 4 + gb) * 64 + gj];
                a1 += red[((c * 3 + 1) * 4 + gb) * 64 + gj];
                a2 += red[((c * 3 + 2) * 4 + gb) * 64 + gj];
            }

            float hprev = hs[((j0 + gj) << 2) + gb];

            const size_t xi = ((size_t)s * 3 * B_SZ + (b0 + gb)) * H_SZ + j0 + gj;
            float x0 = xg[xi];
            float x1 = xg[xi + (size_t)B_SZ * H_SZ];
            float x2 = xg[xi + (size_t)2 * B_SZ * H_SZ];

            float r  = 1.f / (1.f + expf(-(x0 + a0)));
            float z  = 1.f / (1.f + expf(-(x1 + a1)));
            float n  = tanhf(x2 + r * a2);
            float hn = (1.f - z) * n + z * hprev;

            ys[((size_t)s * B_SZ + b0 + gb) * H_SZ + j0 + gj] = hn;
        }

        // HW cluster barrier (release/acquire at cluster scope + L1D flush)
        asm volatile("barrier.cluster.arrive.aligned;" ::: "memory");
        asm volatile("barrier.cluster.wait.aligned;"   ::: "memory");
    }
}

// ---------------- backward shortcut: one GRU step with h = 0 ----------------
__global__ void __launch_bounds__(128) bwd_step(
    const float* __restrict__ xin, long bstride, long off,
    const float* __restrict__ Wi, const float* __restrict__ bias,
    float* __restrict__ hout)
{
    int h = blockIdx.x * 128 + threadIdx.x;
    int b = blockIdx.y;
    const float* xr = xin + (size_t)b * bstride + off;
    const float* W1 = Wi + (size_t)1 * 512 * 512 + h;
    const float* W2 = Wi + (size_t)2 * 512 * 512 + h;
    float a1 = 0.f, a2 = 0.f;
    for (int k = 0; k < 512; k++) {
        float xv = __ldg(xr + k);
        a1 += xv * W1[(size_t)k * 512];
        a2 += xv * W2[(size_t)k * 512];
    }
    float z = 1.f / (1.f + expf(-(a1 + bias[512 + h])));
    float n = tanhf(a2 + bias[1024 + h]);
    hout[(size_t)b * 512 + h] = (1.f - z) * n;
}

// ---------------- final FC ----------------
__global__ void __launch_bounds__(128) fc_kernel(
    const float* __restrict__ ysl, const float* __restrict__ hb,
    const float* __restrict__ fw, const float* __restrict__ fb,
    float* __restrict__ out)
{
    int o = blockIdx.x * 128 + threadIdx.x;
    int b = blockIdx.y;
    float acc = fb[o];
    const float* f0 = ysl + (size_t)b * 512;
    const float* h0 = hb  + (size_t)b * 512;
    for (int jq = 0; jq < 512; jq++) acc += f0[jq] * fw[(size_t)jq * 512 + o];
    for (int jq = 0; jq < 512; jq++) acc += h0[jq] * fw[(size_t)(512 + jq) * 512 + o];
    out[(size_t)b * 512 + o] = acc;
}

// ---------------- launch ----------------
extern "C" void kernel_launch(void* const* d_in, const int* in_sizes, int n_in,
                              void* d_out, int out_size)
{
    (void)in_sizes; (void)n_in; (void)out_size;
    const float* x  = (const float*)d_in[0];   // [64][1024][512]
    const float* Wi = (const float*)d_in[1];   // [2][2][3][512][512]
    const float* Wh = (const float*)d_in[2];   // [2][2][3][512][512]
    const float* bb = (const float*)d_in[3];   // [2][2][3][512]
    const float* fw = (const float*)d_in[4];   // [1024][512]
    const float* fb = (const float*)d_in[5];   // [512]
    float* out = (float*)d_out;

    float *xg, *ys0, *ys1, *hb0, *hb1, *wpk0, *wpk1;
    cudaGetSymbolAddress((void**)&xg,   g_xg);
    cudaGetSymbolAddress((void**)&ys0,  g_ys0);
    cudaGetSymbolAddress((void**)&ys1,  g_ys1);
    cudaGetSymbolAddress((void**)&hb0,  g_hb0);
    cudaGetSymbolAddress((void**)&hb1,  g_hb1);
    cudaGetSymbolAddress((void**)&wpk0, g_wpk0);
    cudaGetSymbolAddress((void**)&wpk1, g_wpk1);

    cudaFuncSetAttribute(scan_kernel, cudaFuncAttributeMaxDynamicSharedMemorySize,
                         SCAN_SMEM_BYTES);

    const size_t WSLAB = (size_t)3 * 512 * 512;
    const size_t BSLAB = (size_t)3 * 512;
    const size_t YSSTEP = (size_t)B_SZ * H_SZ;

    dim3 pgrid(12, 512);
    dim3 sgrid(8, 16);
    int  pkblocks = (3 * 512 * 512 + 255) / 256;

    // pre-pack recurrent weights for both forward layers
    pack_wh<<<pkblocks, 256>>>(Wh + 0 * WSLAB, wpk0);
    pack_wh<<<pkblocks, 256>>>(Wh + 2 * WSLAB, wpk1);

    // ---- forward layer 0 ----
    proj_kernel<<<pgrid, 256>>>(x, (long)S_SZ * I_SZ, (long)I_SZ,
                                Wi + 0 * WSLAB, bb + 0 * BSLAB, xg, S_SZ);
    scan_kernel<<<sgrid, 512, SCAN_SMEM_BYTES>>>(xg, (const float4*)wpk0, ys0, S_SZ);

    // ---- forward layer 1 ----
    proj_kernel<<<pgrid, 256>>>(ys0, (long)H_SZ, (long)B_SZ * H_SZ,
                                Wi + 2 * WSLAB, bb + 2 * BSLAB, xg, S_SZ);
    scan_kernel<<<sgrid, 512, SCAN_SMEM_BYTES>>>(xg, (const float4*)wpk1, ys1, S_SZ);

    // ---- backward direction collapses to two single GRU steps (h0 = 0) ----
    dim3 bgrid(4, 64);
    bwd_step<<<bgrid, 128>>>(x, (long)S_SZ * I_SZ, (long)(S_SZ - 1) * I_SZ,
                             Wi + 1 * WSLAB, bb + 1 * BSLAB, hb0);
    bwd_step<<<bgrid, 128>>>(hb0, (long)H_SZ, 0L,
                             Wi + 3 * WSLAB, bb + 3 * BSLAB, hb1);

    // ---- final FC on [out_f[:, -1], out_b[:, -1]] ----
    fc_kernel<<<bgrid, 128>>>(ys1 + (size_t)(S_SZ - 1) * YSSTEP, hb1, fw, fb, out);
}

// round 8
// speedup vs baseline: 1.0576x; 1.0576x over previous
#include <cuda_runtime.h>
#include <math.h>

#define B_SZ 64
#define S_SZ 1024
#define I_SZ 512
#define H_SZ 512

// ---------------- static device scratch (no allocations allowed) ----------------
__device__ float g_xg  [(size_t)S_SZ * 3 * B_SZ * H_SZ];  // [S][3][B][H]
__device__ float g_ys0 [(size_t)S_SZ * B_SZ * H_SZ];      // layer-0 fwd outputs [S][B][H]
__device__ float g_ys1 [(size_t)S_SZ * B_SZ * H_SZ];      // layer-1 fwd outputs
__device__ float g_hb0 [B_SZ * H_SZ];
__device__ float g_hb1 [B_SZ * H_SZ];
__device__ float g_wpk0[3 * 512 * 512];                   // packed Wh layer0 (fallback path)
__device__ float g_wpk1[3 * 512 * 512];                   // packed Wh layer1 (fallback path)

// ---------------- tf32 helpers ----------------
__device__ __forceinline__ unsigned f2tf(float x) {
    unsigned u;
    asm("cvt.rna.tf32.f32 %0, %1;" : "=r"(u) : "f"(x));
    return u;
}

__device__ __forceinline__ void mma8(float* c, const unsigned* a, unsigned b0, unsigned b1) {
    asm volatile(
        "mma.sync.aligned.m16n8k8.row.col.f32.tf32.tf32.f32 "
        "{%0,%1,%2,%3}, {%4,%5,%6,%7}, {%8,%9}, {%0,%1,%2,%3};"
        : "+f"(c[0]), "+f"(c[1]), "+f"(c[2]), "+f"(c[3])
        : "r"(a[0]), "r"(a[1]), "r"(a[2]), "r"(a[3]), "r"(b0), "r"(b1));
}

__device__ __forceinline__ float f4get(const float4& v, int e) {
    return e == 0 ? v.x : (e == 1 ? v.y : (e == 2 ? v.z : v.w));
}

__device__ __forceinline__ unsigned long long dup_f32(float x) {
    unsigned long long d;
    unsigned b = __float_as_uint(x);
    asm("mov.b64 %0, {%1, %1};" : "=l"(d) : "r"(b));
    return d;
}

__device__ __forceinline__ void fma2(unsigned long long& a,
                                     unsigned long long w, unsigned long long h) {
    asm("fma.rn.f32x2 %0, %1, %2, %0;" : "+l"(a) : "l"(w), "l"(h));
}

// ---------------- projection GEMM (verified working, unchanged) ----------------
__global__ void __launch_bounds__(256) proj_kernel(
    const float* __restrict__ X, long sb, long ss,
    const float* __restrict__ W, const float* __restrict__ bias,
    float* __restrict__ out, int Srows)
{
    __shared__ float As[128][36];
    __shared__ float Bs[32][136];

    const int M  = Srows * B_SZ;
    const int m0 = blockIdx.y * 128;
    const int n0 = blockIdx.x * 128;
    const int g  = n0 >> 9;
    const int h0 = n0 & 511;
    const float* Wg = W + (size_t)g * H_SZ * H_SZ;

    const int tid  = threadIdx.x;
    const int lane = tid & 31;
    const int warp = tid >> 5;
    const int wm   = warp & 3;
    const int wn   = warp >> 2;

    float acc[2][8][4];
#pragma unroll
    for (int i = 0; i < 2; i++)
#pragma unroll
        for (int jf = 0; jf < 8; jf++)
#pragma unroll
            for (int k = 0; k < 4; k++) acc[i][jf][k] = 0.f;

    for (int k0 = 0; k0 < H_SZ; k0 += 32) {
#pragma unroll
        for (int i = 0; i < 4; i++) {
            int idx = tid + i * 256;
            int row = idx >> 3;
            int kk  = (idx & 7) << 2;
            float4 v = make_float4(0.f, 0.f, 0.f, 0.f);
            int r = m0 + row;
            if (r < M) {
                int s = r >> 6, b = r & 63;
                v = *(const float4*)(X + (size_t)b * sb + (size_t)s * ss + k0 + kk);
            }
            As[row][kk + 0] = __uint_as_float(f2tf(v.x));
            As[row][kk + 1] = __uint_as_float(f2tf(v.y));
            As[row][kk + 2] = __uint_as_float(f2tf(v.z));
            As[row][kk + 3] = __uint_as_float(f2tf(v.w));
        }
#pragma unroll
        for (int i = 0; i < 4; i++) {
            int idx = tid + i * 256;
            int kk  = idx >> 5;
            int nn  = (idx & 31) << 2;
            float4 v = *(const float4*)(Wg + (size_t)(k0 + kk) * H_SZ + h0 + nn);
            Bs[kk][nn + 0] = __uint_as_float(f2tf(v.x));
            Bs[kk][nn + 1] = __uint_as_float(f2tf(v.y));
            Bs[kk][nn + 2] = __uint_as_float(f2tf(v.z));
            Bs[kk][nn + 3] = __uint_as_float(f2tf(v.w));
        }
        __syncthreads();

#pragma unroll
        for (int kq = 0; kq < 4; kq++) {
            const int kr = kq * 8;
            unsigned a[2][4];
#pragma unroll
            for (int mf = 0; mf < 2; mf++) {
                int rb = wm * 32 + mf * 16 + (lane >> 2);
                int c  = kr + (lane & 3);
                a[mf][0] = __float_as_uint(As[rb][c]);
                a[mf][1] = __float_as_uint(As[rb + 8][c]);
                a[mf][2] = __float_as_uint(As[rb][c + 4]);
                a[mf][3] = __float_as_uint(As[rb + 8][c + 4]);
            }
#pragma unroll
            for (int nf = 0; nf < 8; nf++) {
                int cb = wn * 64 + nf * 8 + (lane >> 2);
                unsigned b0 = __float_as_uint(Bs[kr + (lane & 3)][cb]);
                unsigned b1 = __float_as_uint(Bs[kr + (lane & 3) + 4][cb]);
                mma8(acc[0][nf], a[0], b0, b1);
                mma8(acc[1][nf], a[1], b0, b1);
            }
        }
        __syncthreads();
    }

#pragma unroll
    for (int mf = 0; mf < 2; mf++) {
#pragma unroll
        for (int nf = 0; nf < 8; nf++) {
            int col = wn * 64 + nf * 8 + ((lane & 3) << 1);
            int h   = h0 + col;
            float b0v = bias[g * H_SZ + h];
            float b1v = bias[g * H_SZ + h + 1];
            int r = m0 + wm * 32 + mf * 16 + (lane >> 2);
            if (r < M) {
                int s = r >> 6, b = r & 63;
                float* o = out + ((size_t)(s * 3 + g) * B_SZ + b) * H_SZ + h;
                o[0] = acc[mf][nf][0] + b0v;
                o[1] = acc[mf][nf][1] + b1v;
            }
            int r2 = r + 8;
            if (r2 < M) {
                int s = r2 >> 6, b = r2 & 63;
                float* o = out + ((size_t)(s * 3 + g) * B_SZ + b) * H_SZ + h;
                o[0] = acc[mf][nf][2] + b0v;
                o[1] = acc[mf][nf][3] + b1v;
            }
        }
    }
}

// ---------------- Wh pre-pack for fallback scan8: [g][k][col] -> [g][k/4][col][k%4] ----------------
__global__ void __launch_bounds__(256) pack_wh(const float* __restrict__ Wh,
                                               float* __restrict__ wpk)
{
    int idx = blockIdx.x * 256 + threadIdx.x;
    if (idx < 3 * 512 * 512) {
        int col = idx & 511;
        int k   = (idx >> 9) & 511;
        int g   = idx >> 18;
        wpk[((((size_t)g * 128 + (k >> 2)) * 512 + col) << 2) + (k & 3)] = Wh[idx];
    }
}

// ================= PRIMARY scan: cluster-16, smem weight cache, f32x2 =================
// grid (16, 8): x = colgroup (32 cols), y = bgrp (8 batches). Cluster = 16 CTAs along x
// (nonportable size, set at launch). Gates 0,1 weight slices cached in smem (131 KB);
// gate 2 streamed from L2. f32x2 lanes = adjacent column pair (weights load as pairs
// directly from raw Wh; only h needs lane duplication).
// Thread map: kc = tid>>5 (32 k rows), bh = (tid>>4)&1 (batch half), cp = tid&15 (col pair).
#define S16_SMEM_BYTES ((32768 + 4096 + 12288) * 4)   // whs 128KB + hs 16KB + red 48KB = 196608

__global__ void __launch_bounds__(512, 1)
scan16_kernel(const float* __restrict__ xg,   // [S][3][B][H]
              const float* __restrict__ Wh,   // [3][512][512] raw slice
              float* __restrict__ ys,         // [S][B][H]
              int S)
{
    extern __shared__ float sm[];
    float*  whs = sm;                     // [2][512][32]: gates 0,1, cols j0..j0+31
    float*  hs  = sm + 32768;             // [8][512]
    float4* hs4 = (float4*)hs;
    float*  red = sm + 32768 + 4096;      // [16 kc][3 g][8 b][32 col]

    const int tid = threadIdx.x;
    const int cp  = tid & 15;             // column pair index (cols 2cp, 2cp+1)
    const int bh  = (tid >> 4) & 1;       // batch half (b 0-3 / 4-7)
    const int kc  = tid >> 5;             // 0..15, 32 K-rows each
    const int j0  = blockIdx.x << 5;      // 32 cols per CTA
    const int b0  = blockIdx.y << 3;

    // one-time cache of gates 0,1 weight slices (coalesced over cols)
    for (int i = tid; i < 2 * 512 * 32; i += 512) {
        int j = i & 31;
        int r = i >> 5;                   // g*512 + k
        whs[i] = Wh[((size_t)r << 9) + j0 + j];
    }

    const int gb = tid >> 5;              // gate stage (tid < 256)
    const int gj = tid & 31;

    const char* w2base = (const char*)(Wh + ((size_t)(2 * 512) << 9) + j0 + (cp << 1));
    const int   kbase  = kc << 5;

    for (int s = 0; s < S; s++) {
        // stage h_prev [8][512] coalesced (round-6 pattern)
        if (s == 0) {
            for (int i = tid; i < 1024; i += 512) hs4[i] = make_float4(0.f, 0.f, 0.f, 0.f);
        } else {
            const float4* hp = (const float4*)(ys + ((size_t)(s - 1) * B_SZ + b0) * H_SZ);
            for (int i = tid; i < 1024; i += 512) hs4[i] = __ldcg(hp + i);
        }
        __syncthreads();   // also orders the one-time whs fill before first use

        unsigned long long acc[3][4];
#pragma unroll
        for (int g = 0; g < 3; g++)
#pragma unroll
            for (int b = 0; b < 4; b++) acc[g][b] = 0ull;

#pragma unroll
        for (int t = 0; t < 8; t++) {
            const int k4 = (kbase >> 2) + t;
            unsigned long long w0[4], w1[4], w2[4];
#pragma unroll
            for (int e = 0; e < 4; e++) {
                const int k = kbase + (t << 2) + e;
                w0[e] = *(const unsigned long long*)&whs[((0 * 512 + k) << 5) + (cp << 1)];
                w1[e] = *(const unsigned long long*)&whs[((1 * 512 + k) << 5) + (cp << 1)];
                w2[e] = __ldg((const unsigned long long*)(w2base + ((size_t)k << 11)));
            }
            float4 h4[4];
#pragma unroll
            for (int b = 0; b < 4; b++)
                h4[b] = hs4[(((bh << 2) + b) << 7) + k4];
#pragma unroll
            for (int e = 0; e < 4; e++) {
#pragma unroll
                for (int b = 0; b < 4; b++) {
                    unsigned long long hd = dup_f32(f4get(h4[b], e));
                    fma2(acc[0][b], w0[e], hd);
                    fma2(acc[1][b], w1[e], hd);
                    fma2(acc[2][b], w2[e], hd);
                }
            }
        }

        // cross-kc partials
#pragma unroll
        for (int g = 0; g < 3; g++)
#pragma unroll
            for (int b = 0; b < 4; b++) {
                unsigned r0, r1;
                asm("mov.b64 {%0, %1}, %2;" : "=r"(r0), "=r"(r1) : "l"(acc[g][b]));
                float* rp = &red[(((kc * 3 + g) * 8) + ((bh << 2) + b)) * 32 + (cp << 1)];
                rp[0] = __uint_as_float(r0);
                rp[1] = __uint_as_float(r1);
            }
        __syncthreads();

        // gate stage: 256 threads, one per (batch gb, col gj)
        if (tid < 256) {
            float a0 = 0.f, a1 = 0.f, a2 = 0.f;
#pragma unroll
            for (int c = 0; c < 16; c++) {
                a0 += red[((c * 3 + 0) * 8 + gb) * 32 + gj];
                a1 += red[((c * 3 + 1) * 8 + gb) * 32 + gj];
                a2 += red[((c * 3 + 2) * 8 + gb) * 32 + gj];
            }

            float hprev = hs[gb * 512 + j0 + gj];

            const size_t xi = ((size_t)s * 3 * B_SZ + (b0 + gb)) * H_SZ + j0 + gj;
            float x0 = xg[xi];
            float x1 = xg[xi + (size_t)B_SZ * H_SZ];
            float x2 = xg[xi + (size_t)2 * B_SZ * H_SZ];

            float r  = 1.f / (1.f + expf(-(x0 + a0)));
            float z  = 1.f / (1.f + expf(-(x1 + a1)));
            float n  = tanhf(x2 + r * a2);
            float hn = (1.f - z) * n + z * hprev;

            ys[((size_t)s * B_SZ + b0 + gb) * H_SZ + j0 + gj] = hn;
        }

        // HW cluster barrier (release/acquire at cluster scope)
        asm volatile("barrier.cluster.arrive.aligned;" ::: "memory");
        asm volatile("barrier.cluster.wait.aligned;"   ::: "memory");
    }
}

// ================= FALLBACK scan: exact round-6 kernel (cluster 8, streamed weights) =================
#define SCAN8_SMEM_BYTES ((4096 + 12288) * 4)   // 64 KB

__global__ void __launch_bounds__(512, 1) __cluster_dims__(8, 1, 1)
scan8_kernel(const float* __restrict__ xg,    // [S][3][B][H]
             const float4* __restrict__ wpk,  // [3][128][512] float4 (packed)
             float* __restrict__ ys,          // [S][B][H]
             int S)
{
    extern __shared__ float sm[];
    float*  hs  = sm;
    float*  red = sm + 4096;
    float4* hs4 = (float4*)hs;

    const int tid  = threadIdx.x;
    const int lane = tid & 31;
    const int w    = tid >> 5;
    const int kc   = w >> 1;
    const int jh   = w & 1;
    const int cgrp = blockIdx.x;
    const int bgrp = blockIdx.y;
    const int j0   = cgrp << 6;
    const int b0   = bgrp << 3;
    const int col  = j0 + (jh << 5) + lane;
    const int k4b  = kc << 4;
    const int jc   = (jh << 5) + lane;

    const int gb = tid >> 6;
    const int gj = tid & 63;

    const float4* w0p = wpk + ((size_t)(0 * 128 + k4b) << 9) + col;
    const float4* w1p = wpk + ((size_t)(1 * 128 + k4b) << 9) + col;
    const float4* w2p = wpk + ((size_t)(2 * 128 + k4b) << 9) + col;

    for (int s = 0; s < S; s++) {
        if (s == 0) {
            for (int i = tid; i < 1024; i += 512) hs4[i] = make_float4(0.f, 0.f, 0.f, 0.f);
        } else {
            const float4* hp = (const float4*)(ys + ((size_t)(s - 1) * B_SZ + b0) * H_SZ);
            for (int i = tid; i < 1024; i += 512) hs4[i] = __ldcg(hp + i);
        }
        __syncthreads();

        float acc[3][8];
#pragma unroll
        for (int g = 0; g < 3; g++)
#pragma unroll
            for (int b = 0; b < 8; b++) acc[g][b] = 0.f;

#pragma unroll 4
        for (int t = 0; t < 16; t++) {
            float4 w0 = __ldg(w0p + ((size_t)t << 9));
            float4 w1 = __ldg(w1p + ((size_t)t << 9));
            float4 w2 = __ldg(w2p + ((size_t)t << 9));
            const int k4 = k4b + t;
#pragma unroll
            for (int b = 0; b < 8; b++) {
                float4 h4 = hs4[b * 128 + k4];
                acc[0][b] += h4.x * w0.x + h4.y * w0.y + h4.z * w0.z + h4.w * w0.w;
                acc[1][b] += h4.x * w1.x + h4.y * w1.y + h4.z * w1.z + h4.w * w1.w;
                acc[2][b] += h4.x * w2.x + h4.y * w2.y + h4.z * w2.z + h4.w * w2.w;
            }
        }

#pragma unroll
        for (int g = 0; g < 3; g++)
#pragma unroll
            for (int b = 0; b < 8; b++)
                red[((kc * 3 + g) * 8 + b) * 64 + jc] = acc[g][b];
        __syncthreads();

        float a0 = 0.f, a1 = 0.f, a2 = 0.f;
#pragma unroll
        for (int c = 0; c < 8; c++) {
            a0 += red[((c * 3 + 0) * 8 + gb) * 64 + gj];
            a1 += red[((c * 3 + 1) * 8 + gb) * 64 + gj];
            a2 += red[((c * 3 + 2) * 8 + gb) * 64 + gj];
        }

        float hprev = hs[gb * 512 + j0 + gj];

        const size_t xi = ((size_t)s * 3 * B_SZ + (b0 + gb)) * H_SZ + j0 + gj;
        float x0 = xg[xi];
        float x1 = xg[xi + (size_t)B_SZ * H_SZ];
        float x2 = xg[xi + (size_t)2 * B_SZ * H_SZ];

        float r  = 1.f / (1.f + expf(-(x0 + a0)));
        float z  = 1.f / (1.f + expf(-(x1 + a1)));
        float n  = tanhf(x2 + r * a2);
        float hn = (1.f - z) * n + z * hprev;

        ys[((size_t)s * B_SZ + b0 + gb) * H_SZ + j0 + gj] = hn;

        asm volatile("barrier.cluster.arrive.aligned;" ::: "memory");
        asm volatile("barrier.cluster.wait.aligned;"   ::: "memory");
    }
}

// ---------------- backward shortcut: one GRU step with h = 0 ----------------
__global__ void __launch_bounds__(128) bwd_step(
    const float* __restrict__ xin, long bstride, long off,
    const float* __restrict__ Wi, const float* __restrict__ bias,
    float* __restrict__ hout)
{
    int h = blockIdx.x * 128 + threadIdx.x;
    int b = blockIdx.y;
    const float* xr = xin + (size_t)b * bstride + off;
    const float* W1 = Wi + (size_t)1 * 512 * 512 + h;
    const float* W2 = Wi + (size_t)2 * 512 * 512 + h;
    float a1 = 0.f, a2 = 0.f;
    for (int k = 0; k < 512; k++) {
        float xv = __ldg(xr + k);
        a1 += xv * W1[(size_t)k * 512];
        a2 += xv * W2[(size_t)k * 512];
    }
    float z = 1.f / (1.f + expf(-(a1 + bias[512 + h])));
    float n = tanhf(a2 + bias[1024 + h]);
    hout[(size_t)b * 512 + h] = (1.f - z) * n;
}

// ---------------- final FC ----------------
__global__ void __launch_bounds__(128) fc_kernel(
    const float* __restrict__ ysl, const float* __restrict__ hb,
    const float* __restrict__ fw, const float* __restrict__ fb,
    float* __restrict__ out)
{
    int o = blockIdx.x * 128 + threadIdx.x;
    int b = blockIdx.y;
    float acc = fb[o];
    const float* f0 = ysl + (size_t)b * 512;
    const float* h0 = hb  + (size_t)b * 512;
    for (int jq = 0; jq < 512; jq++) acc += f0[jq] * fw[(size_t)jq * 512 + o];
    for (int jq = 0; jq < 512; jq++) acc += h0[jq] * fw[(size_t)(512 + jq) * 512 + o];
    out[(size_t)b * 512 + o] = acc;
}

// ---------------- launch ----------------
extern "C" void kernel_launch(void* const* d_in, const int* in_sizes, int n_in,
                              void* d_out, int out_size)
{
    (void)in_sizes; (void)n_in; (void)out_size;
    const float* x  = (const float*)d_in[0];   // [64][1024][512]
    const float* Wi = (const float*)d_in[1];   // [2][2][3][512][512]
    const float* Wh = (const float*)d_in[2];   // [2][2][3][512][512]
    const float* bb = (const float*)d_in[3];   // [2][2][3][512]
    const float* fw = (const float*)d_in[4];   // [1024][512]
    const float* fb = (const float*)d_in[5];   // [512]
    float* out = (float*)d_out;

    float *xg, *ys0, *ys1, *hb0, *hb1, *wpk0, *wpk1;
    cudaGetSymbolAddress((void**)&xg,   g_xg);
    cudaGetSymbolAddress((void**)&ys0,  g_ys0);
    cudaGetSymbolAddress((void**)&ys1,  g_ys1);
    cudaGetSymbolAddress((void**)&hb0,  g_hb0);
    cudaGetSymbolAddress((void**)&hb1,  g_hb1);
    cudaGetSymbolAddress((void**)&wpk0, g_wpk0);
    cudaGetSymbolAddress((void**)&wpk1, g_wpk1);

    cudaFuncSetAttribute(scan16_kernel, cudaFuncAttributeMaxDynamicSharedMemorySize,
                         S16_SMEM_BYTES);
    cudaFuncSetAttribute(scan16_kernel, cudaFuncAttributeNonPortableClusterSizeAllowed, 1);
    cudaFuncSetAttribute(scan8_kernel, cudaFuncAttributeMaxDynamicSharedMemorySize,
                         SCAN8_SMEM_BYTES);

    // runtime capability check: can we launch 16-CTA clusters for scan16?
    int maxc = 0;
    {
        cudaLaunchConfig_t qcfg = {};
        qcfg.gridDim = dim3(16, 8);
        qcfg.blockDim = dim3(512);
        qcfg.dynamicSmemBytes = S16_SMEM_BYTES;
        if (cudaOccupancyMaxPotentialClusterSize(&maxc, scan16_kernel, &qcfg) != cudaSuccess)
            maxc = 0;
    }
    const bool use16 = (maxc >= 16);

    const size_t WSLAB = (size_t)3 * 512 * 512;
    const size_t BSLAB = (size_t)3 * 512;
    const size_t YSSTEP = (size_t)B_SZ * H_SZ;

    dim3 pgrid(12, 512);
    int  pkblocks = (3 * 512 * 512 + 255) / 256;

    if (!use16) {   // fallback needs packed weights
        pack_wh<<<pkblocks, 256>>>(Wh + 0 * WSLAB, wpk0);
        pack_wh<<<pkblocks, 256>>>(Wh + 2 * WSLAB, wpk1);
    }

    auto launch_scan = [&](const float* xgp, const float* whraw, const float* wpkp, float* ysp) {
        if (use16) {
            cudaLaunchConfig_t cfg = {};
            cfg.gridDim = dim3(16, 8);
            cfg.blockDim = dim3(512);
            cfg.dynamicSmemBytes = S16_SMEM_BYTES;
            cfg.stream = 0;
            cudaLaunchAttribute at[1];
            at[0].id = cudaLaunchAttributeClusterDimension;
            at[0].val.clusterDim.x = 16;
            at[0].val.clusterDim.y = 1;
            at[0].val.clusterDim.z = 1;
            cfg.attrs = at;
            cfg.numAttrs = 1;
            int S = S_SZ;
            cudaLaunchKernelEx(&cfg, scan16_kernel, xgp, whraw, ysp, S);
        } else {
            scan8_kernel<<<dim3(8, 8), 512, SCAN8_SMEM_BYTES>>>(
                xgp, (const float4*)wpkp, ysp, S_SZ);
        }
    };

    // ---- forward layer 0 ----
    proj_kernel<<<pgrid, 256>>>(x, (long)S_SZ * I_SZ, (long)I_SZ,
                                Wi + 0 * WSLAB, bb + 0 * BSLAB, xg, S_SZ);
    launch_scan(xg, Wh + 0 * WSLAB, wpk0, ys0);

    // ---- forward layer 1 ----
    proj_kernel<<<pgrid, 256>>>(ys0, (long)H_SZ, (long)B_SZ * H_SZ,
                                Wi + 2 * WSLAB, bb + 2 * BSLAB, xg, S_SZ);
    launch_scan(xg, Wh + 2 * WSLAB, wpk1, ys1);

    // ---- backward direction collapses to two single GRU steps (h0 = 0) ----
    dim3 bgrid(4, 64);
    bwd_step<<<bgrid, 128>>>(x, (long)S_SZ * I_SZ, (long)(S_SZ - 1) * I_SZ,
                             Wi + 1 * WSLAB, bb + 1 * BSLAB, hb0);
    bwd_step<<<bgrid, 128>>>(hb0, (long)H_SZ, 0L,
                             Wi + 3 * WSLAB, bb + 3 * BSLAB, hb1);

    // ---- final FC on [out_f[:, -1], out_b[:, -1]] ----
    fc_kernel<<<bgrid, 128>>>(ys1 + (size_t)(S_SZ - 1) * YSSTEP, hb1, fw, fb, out);
}

// round 9
// speedup vs baseline: 1.1605x; 1.0972x over previous
#include <cuda_runtime.h>
#include <math.h>

#define B_SZ 64
#define S_SZ 1024
#define I_SZ 512
#define H_SZ 512

// ---------------- static device scratch (no allocations allowed) ----------------
__device__ float g_xg  [(size_t)S_SZ * 3 * B_SZ * H_SZ];  // [S][3][B][H]
__device__ float g_ys0 [(size_t)S_SZ * B_SZ * H_SZ];      // layer-0 fwd outputs [S][B][H]
__device__ float g_ys1 [(size_t)S_SZ * B_SZ * H_SZ];      // layer-1 fwd outputs
__device__ float g_hb0 [B_SZ * H_SZ];
__device__ float g_hb1 [B_SZ * H_SZ];
__device__ float g_wpk0[3 * 512 * 512];                   // packed Wh layer0 (fallback path)
__device__ float g_wpk1[3 * 512 * 512];                   // packed Wh layer1 (fallback path)

// ---------------- tf32 helpers ----------------
__device__ __forceinline__ unsigned f2tf(float x) {
    unsigned u;
    asm("cvt.rna.tf32.f32 %0, %1;" : "=r"(u) : "f"(x));
    return u;
}

__device__ __forceinline__ void mma8(float* c, const unsigned* a, unsigned b0, unsigned b1) {
    asm volatile(
        "mma.sync.aligned.m16n8k8.row.col.f32.tf32.tf32.f32 "
        "{%0,%1,%2,%3}, {%4,%5,%6,%7}, {%8,%9}, {%0,%1,%2,%3};"
        : "+f"(c[0]), "+f"(c[1]), "+f"(c[2]), "+f"(c[3])
        : "r"(a[0]), "r"(a[1]), "r"(a[2]), "r"(a[3]), "r"(b0), "r"(b1));
}

__device__ __forceinline__ unsigned long long dup_f32(float x) {
    unsigned long long d;
    unsigned b = __float_as_uint(x);
    asm("mov.b64 %0, {%1, %1};" : "=l"(d) : "r"(b));
    return d;
}

__device__ __forceinline__ void fma2(unsigned long long& a,
                                     unsigned long long w, unsigned long long h) {
    asm("fma.rn.f32x2 %0, %1, %2, %0;" : "+l"(a) : "l"(w), "l"(h));
}

// ---------------- projection GEMM (verified working, unchanged) ----------------
__global__ void __launch_bounds__(256) proj_kernel(
    const float* __restrict__ X, long sb, long ss,
    const float* __restrict__ W, const float* __restrict__ bias,
    float* __restrict__ out, int Srows)
{
    __shared__ float As[128][36];
    __shared__ float Bs[32][136];

    const int M  = Srows * B_SZ;
    const int m0 = blockIdx.y * 128;
    const int n0 = blockIdx.x * 128;
    const int g  = n0 >> 9;
    const int h0 = n0 & 511;
    const float* Wg = W + (size_t)g * H_SZ * H_SZ;

    const int tid  = threadIdx.x;
    const int lane = tid & 31;
    const int warp = tid >> 5;
    const int wm   = warp & 3;
    const int wn   = warp >> 2;

    float acc[2][8][4];
#pragma unroll
    for (int i = 0; i < 2; i++)
#pragma unroll
        for (int jf = 0; jf < 8; jf++)
#pragma unroll
            for (int k = 0; k < 4; k++) acc[i][jf][k] = 0.f;

    for (int k0 = 0; k0 < H_SZ; k0 += 32) {
#pragma unroll
        for (int i = 0; i < 4; i++) {
            int idx = tid + i * 256;
            int row = idx >> 3;
            int kk  = (idx & 7) << 2;
            float4 v = make_float4(0.f, 0.f, 0.f, 0.f);
            int r = m0 + row;
            if (r < M) {
                int s = r >> 6, b = r & 63;
                v = *(const float4*)(X + (size_t)b * sb + (size_t)s * ss + k0 + kk);
            }
            As[row][kk + 0] = __uint_as_float(f2tf(v.x));
            As[row][kk + 1] = __uint_as_float(f2tf(v.y));
            As[row][kk + 2] = __uint_as_float(f2tf(v.z));
            As[row][kk + 3] = __uint_as_float(f2tf(v.w));
        }
#pragma unroll
        for (int i = 0; i < 4; i++) {
            int idx = tid + i * 256;
            int kk  = idx >> 5;
            int nn  = (idx & 31) << 2;
            float4 v = *(const float4*)(Wg + (size_t)(k0 + kk) * H_SZ + h0 + nn);
            Bs[kk][nn + 0] = __uint_as_float(f2tf(v.x));
            Bs[kk][nn + 1] = __uint_as_float(f2tf(v.y));
            Bs[kk][nn + 2] = __uint_as_float(f2tf(v.z));
            Bs[kk][nn + 3] = __uint_as_float(f2tf(v.w));
        }
        __syncthreads();

#pragma unroll
        for (int kq = 0; kq < 4; kq++) {
            const int kr = kq * 8;
            unsigned a[2][4];
#pragma unroll
            for (int mf = 0; mf < 2; mf++) {
                int rb = wm * 32 + mf * 16 + (lane >> 2);
                int c  = kr + (lane & 3);
                a[mf][0] = __float_as_uint(As[rb][c]);
                a[mf][1] = __float_as_uint(As[rb + 8][c]);
                a[mf][2] = __float_as_uint(As[rb][c + 4]);
                a[mf][3] = __float_as_uint(As[rb + 8][c + 4]);
            }
#pragma unroll
            for (int nf = 0; nf < 8; nf++) {
                int cb = wn * 64 + nf * 8 + (lane >> 2);
                unsigned b0 = __float_as_uint(Bs[kr + (lane & 3)][cb]);
                unsigned b1 = __float_as_uint(Bs[kr + (lane & 3) + 4][cb]);
                mma8(acc[0][nf], a[0], b0, b1);
                mma8(acc[1][nf], a[1], b0, b1);
            }
        }
        __syncthreads();
    }

#pragma unroll
    for (int mf = 0; mf < 2; mf++) {
#pragma unroll
        for (int nf = 0; nf < 8; nf++) {
            int col = wn * 64 + nf * 8 + ((lane & 3) << 1);
            int h   = h0 + col;
            float b0v = bias[g * H_SZ + h];
            float b1v = bias[g * H_SZ + h + 1];
            int r = m0 + wm * 32 + mf * 16 + (lane >> 2);
            if (r < M) {
                int s = r >> 6, b = r & 63;
                float* o = out + ((size_t)(s * 3 + g) * B_SZ + b) * H_SZ + h;
                o[0] = acc[mf][nf][0] + b0v;
                o[1] = acc[mf][nf][1] + b1v;
            }
            int r2 = r + 8;
            if (r2 < M) {
                int s = r2 >> 6, b = r2 & 63;
                float* o = out + ((size_t)(s * 3 + g) * B_SZ + b) * H_SZ + h;
                o[0] = acc[mf][nf][2] + b0v;
                o[1] = acc[mf][nf][3] + b1v;
            }
        }
    }
}

// ---------------- Wh pre-pack for fallback scan8: [g][k][col] -> [g][k/4][col][k%4] ----------------
__global__ void __launch_bounds__(256) pack_wh(const float* __restrict__ Wh,
                                               float* __restrict__ wpk)
{
    int idx = blockIdx.x * 256 + threadIdx.x;
    if (idx < 3 * 512 * 512) {
        int col = idx & 511;
        int k   = (idx >> 9) & 511;
        int g   = idx >> 18;
        wpk[((((size_t)g * 128 + (k >> 2)) * 512 + col) << 2) + (k & 3)] = Wh[idx];
    }
}

// ================= PRIMARY scan: persistent register weights + f32x2 col-pairs =================
// grid (16, 8): x = colgroup (32 cols), y = bgrp (8 batches). Cluster = 16 CTAs along x.
// Thread (cp = tid&15, kc = tid>>4): owns cols (j0+2cp, j0+2cp+1) x k-chunk [kc*16, kc*16+16)
// for all 3 gates -> 48 weight PAIRS (96 regs) loaded ONCE, reused for all S steps.
// Inner product via fma.rn.f32x2 (lanes = column pair); h broadcast from smem + lane-dup mov.
#define S16R_SMEM_BYTES ((4096 + 24576) * 4)   // hs 16KB + red 96KB = 114688 B

__global__ void __launch_bounds__(512, 1)
scan16r_kernel(const float* __restrict__ xg,   // [S][3][B][H]
               const float* __restrict__ Wh,   // [3][512][512] raw slice
               float* __restrict__ ys,         // [S][B][H]
               int S)
{
    extern __shared__ float sm[];
    float*  hs  = sm;                 // [8][512]
    float4* hs4 = (float4*)hs;
    float*  red = sm + 4096;          // [32 kc][3 g][8 b][32 col]

    const int tid   = threadIdx.x;
    const int cp    = tid & 15;       // column-pair index (cols 2cp, 2cp+1)
    const int kc    = tid >> 4;       // 0..31, k-chunk of 16
    const int j0    = blockIdx.x << 5;
    const int b0    = blockIdx.y << 3;
    const int kbase = kc << 4;

    // persistent weights: wr[g*16+kk] = 64-bit pair Wh[g][kbase+kk][j0+2cp .. +1]
    unsigned long long wr[48];
#pragma unroll
    for (int g = 0; g < 3; g++)
#pragma unroll
        for (int kk = 0; kk < 16; kk++)
            wr[g * 16 + kk] = __ldg((const unsigned long long*)
                (Wh + (((size_t)g * 512 + kbase + kk) << 9) + j0) + cp);

    // gate-stage mapping (tid < 256): gb = batch-local, gj = col-local
    const int gb = tid >> 5;
    const int gj = tid & 31;

    for (int s = 0; s < S; s++) {
        // prefetch xg gate operands early (hide DRAM latency behind matvec)
        float x0 = 0.f, x1 = 0.f, x2 = 0.f;
        if (tid < 256) {
            const size_t xi = ((size_t)s * 3 * B_SZ + (b0 + gb)) * H_SZ + j0 + gj;
            x0 = __ldg(xg + xi);
            x1 = __ldg(xg + xi + (size_t)B_SZ * H_SZ);
            x2 = __ldg(xg + xi + (size_t)2 * B_SZ * H_SZ);
        }

        // stage h_prev [8][512] coalesced (round-6 pattern)
        if (s == 0) {
            for (int i = tid; i < 1024; i += 512) hs4[i] = make_float4(0.f, 0.f, 0.f, 0.f);
        } else {
            const float4* hp = (const float4*)(ys + ((size_t)(s - 1) * B_SZ + b0) * H_SZ);
            for (int i = tid; i < 1024; i += 512) hs4[i] = __ldcg(hp + i);
        }
        __syncthreads();

        // matvec: for each batch, 48 fma2 from register weights; h via broadcast LDS
#pragma unroll 1
        for (int b = 0; b < 8; b++) {
            const float4* hb = hs4 + (b << 7) + (kbase >> 2);
            unsigned long long a0 = 0ull, a1 = 0ull, a2 = 0ull;
#pragma unroll
            for (int q = 0; q < 4; q++) {
                float4 h4 = hb[q];
                unsigned long long hd;
                hd = dup_f32(h4.x);
                fma2(a0, wr[q * 4 + 0], hd);
                fma2(a1, wr[16 + q * 4 + 0], hd);
                fma2(a2, wr[32 + q * 4 + 0], hd);
                hd = dup_f32(h4.y);
                fma2(a0, wr[q * 4 + 1], hd);
                fma2(a1, wr[16 + q * 4 + 1], hd);
                fma2(a2, wr[32 + q * 4 + 1], hd);
                hd = dup_f32(h4.z);
                fma2(a0, wr[q * 4 + 2], hd);
                fma2(a1, wr[16 + q * 4 + 2], hd);
                fma2(a2, wr[32 + q * 4 + 2], hd);
                hd = dup_f32(h4.w);
                fma2(a0, wr[q * 4 + 3], hd);
                fma2(a1, wr[16 + q * 4 + 3], hd);
                fma2(a2, wr[32 + q * 4 + 3], hd);
            }
            // write 64-bit partial pairs (8B aligned: col index 2cp is even)
            *(unsigned long long*)&red[((kc * 3 + 0) * 8 + b) * 32 + (cp << 1)] = a0;
            *(unsigned long long*)&red[((kc * 3 + 1) * 8 + b) * 32 + (cp << 1)] = a1;
            *(unsigned long long*)&red[((kc * 3 + 2) * 8 + b) * 32 + (cp << 1)] = a2;
        }
        __syncthreads();

        // gate stage: 256 threads, one per (batch gb, col gj); 32-way kc reduction
        if (tid < 256) {
            float s0 = 0.f, s1 = 0.f, s2 = 0.f;
#pragma unroll
            for (int c = 0; c < 32; c++) {
                s0 += red[((c * 3 + 0) * 8 + gb) * 32 + gj];
                s1 += red[((c * 3 + 1) * 8 + gb) * 32 + gj];
                s2 += red[((c * 3 + 2) * 8 + gb) * 32 + gj];
            }

            float hprev = hs[gb * 512 + j0 + gj];

            float r  = 1.f / (1.f + expf(-(x0 + s0)));
            float z  = 1.f / (1.f + expf(-(x1 + s1)));
            float n  = tanhf(x2 + r * s2);
            float hn = (1.f - z) * n + z * hprev;

            ys[((size_t)s * B_SZ + b0 + gb) * H_SZ + j0 + gj] = hn;
        }

        // HW cluster barrier (release/acquire at cluster scope)
        asm volatile("barrier.cluster.arrive.aligned;" ::: "memory");
        asm volatile("barrier.cluster.wait.aligned;"   ::: "memory");
    }
}

// ================= FALLBACK scan: exact round-6 kernel (cluster 8, streamed weights) =================
#define SCAN8_SMEM_BYTES ((4096 + 12288) * 4)   // 64 KB

__global__ void __launch_bounds__(512, 1) __cluster_dims__(8, 1, 1)
scan8_kernel(const float* __restrict__ xg,    // [S][3][B][H]
             const float4* __restrict__ wpk,  // [3][128][512] float4 (packed)
             float* __restrict__ ys,          // [S][B][H]
             int S)
{
    extern __shared__ float sm[];
    float*  hs  = sm;
    float*  red = sm + 4096;
    float4* hs4 = (float4*)hs;

    const int tid  = threadIdx.x;
    const int lane = tid & 31;
    const int w    = tid >> 5;
    const int kc   = w >> 1;
    const int jh   = w & 1;
    const int j0   = blockIdx.x << 6;
    const int b0   = blockIdx.y << 3;
    const int col  = j0 + (jh << 5) + lane;
    const int k4b  = kc << 4;
    const int jc   = (jh << 5) + lane;

    const int gb = tid >> 6;
    const int gj = tid & 63;

    const float4* w0p = wpk + ((size_t)(0 * 128 + k4b) << 9) + col;
    const float4* w1p = wpk + ((size_t)(1 * 128 + k4b) << 9) + col;
    const float4* w2p = wpk + ((size_t)(2 * 128 + k4b) << 9) + col;

    for (int s = 0; s < S; s++) {
        if (s == 0) {
            for (int i = tid; i < 1024; i += 512) hs4[i] = make_float4(0.f, 0.f, 0.f, 0.f);
        } else {
            const float4* hp = (const float4*)(ys + ((size_t)(s - 1) * B_SZ + b0) * H_SZ);
            for (int i = tid; i < 1024; i += 512) hs4[i] = __ldcg(hp + i);
        }
        __syncthreads();

        float acc[3][8];
#pragma unroll
        for (int g = 0; g < 3; g++)
#pragma unroll
            for (int b = 0; b < 8; b++) acc[g][b] = 0.f;

#pragma unroll 4
        for (int t = 0; t < 16; t++) {
            float4 w0 = __ldg(w0p + ((size_t)t << 9));
            float4 w1 = __ldg(w1p + ((size_t)t << 9));
            float4 w2 = __ldg(w2p + ((size_t)t << 9));
            const int k4 = k4b + t;
#pragma unroll
            for (int b = 0; b < 8; b++) {
                float4 h4 = hs4[b * 128 + k4];
                acc[0][b] += h4.x * w0.x + h4.y * w0.y + h4.z * w0.z + h4.w * w0.w;
                acc[1][b] += h4.x * w1.x + h4.y * w1.y + h4.z * w1.z + h4.w * w1.w;
                acc[2][b] += h4.x * w2.x + h4.y * w2.y + h4.z * w2.z + h4.w * w2.w;
            }
        }

#pragma unroll
        for (int g = 0; g < 3; g++)
#pragma unroll
            for (int b = 0; b < 8; b++)
                red[((kc * 3 + g) * 8 + b) * 64 + jc] = acc[g][b];
        __syncthreads();

        float a0 = 0.f, a1 = 0.f, a2 = 0.f;
#pragma unroll
        for (int c = 0; c < 8; c++) {
            a0 += red[((c * 3 + 0) * 8 + gb) * 64 + gj];
            a1 += red[((c * 3 + 1) * 8 + gb) * 64 + gj];
            a2 += red[((c * 3 + 2) * 8 + gb) * 64 + gj];
        }

        float hprev = hs[gb * 512 + j0 + gj];

        const size_t xi = ((size_t)s * 3 * B_SZ + (b0 + gb)) * H_SZ + j0 + gj;
        float x0 = xg[xi];
        float x1 = xg[xi + (size_t)B_SZ * H_SZ];
        float x2 = xg[xi + (size_t)2 * B_SZ * H_SZ];

        float r  = 1.f / (1.f + expf(-(x0 + a0)));
        float z  = 1.f / (1.f + expf(-(x1 + a1)));
        float n  = tanhf(x2 + r * a2);
        float hn = (1.f - z) * n + z * hprev;

        ys[((size_t)s * B_SZ + b0 + gb) * H_SZ + j0 + gj] = hn;

        asm volatile("barrier.cluster.arrive.aligned;" ::: "memory");
        asm volatile("barrier.cluster.wait.aligned;"   ::: "memory");
    }
}

// ---------------- backward shortcut: one GRU step with h = 0 ----------------
__global__ void __launch_bounds__(128) bwd_step(
    const float* __restrict__ xin, long bstride, long off,
    const float* __restrict__ Wi, const float* __restrict__ bias,
    float* __restrict__ hout)
{
    int h = blockIdx.x * 128 + threadIdx.x;
    int b = blockIdx.y;
    const float* xr = xin + (size_t)b * bstride + off;
    const float* W1 = Wi + (size_t)1 * 512 * 512 + h;
    const float* W2 = Wi + (size_t)2 * 512 * 512 + h;
    float a1 = 0.f, a2 = 0.f;
    for (int k = 0; k < 512; k++) {
        float xv = __ldg(xr + k);
        a1 += xv * W1[(size_t)k * 512];
        a2 += xv * W2[(size_t)k * 512];
    }
    float z = 1.f / (1.f + expf(-(a1 + bias[512 + h])));
    float n = tanhf(a2 + bias[1024 + h]);
    hout[(size_t)b * 512 + h] = (1.f - z) * n;
}

// ---------------- final FC ----------------
__global__ void __launch_bounds__(128) fc_kernel(
    const float* __restrict__ ysl, const float* __restrict__ hb,
    const float* __restrict__ fw, const float* __restrict__ fb,
    float* __restrict__ out)
{
    int o = blockIdx.x * 128 + threadIdx.x;
    int b = blockIdx.y;
    float acc = fb[o];
    const float* f0 = ysl + (size_t)b * 512;
    const float* h0 = hb  + (size_t)b * 512;
    for (int jq = 0; jq < 512; jq++) acc += f0[jq] * fw[(size_t)jq * 512 + o];
    for (int jq = 0; jq < 512; jq++) acc += h0[jq] * fw[(size_t)(512 + jq) * 512 + o];
    out[(size_t)b * 512 + o] = acc;
}

// ---------------- launch ----------------
extern "C" void kernel_launch(void* const* d_in, const int* in_sizes, int n_in,
                              void* d_out, int out_size)
{
    (void)in_sizes; (void)n_in; (void)out_size;
    const float* x  = (const float*)d_in[0];   // [64][1024][512]
    const float* Wi = (const float*)d_in[1];   // [2][2][3][512][512]
    const float* Wh = (const float*)d_in[2];   // [2][2][3][512][512]
    const float* bb = (const float*)d_in[3];   // [2][2][3][512]
    const float* fw = (const float*)d_in[4];   // [1024][512]
    const float* fb = (const float*)d_in[5];   // [512]
    float* out = (float*)d_out;

    float *xg, *ys0, *ys1, *hb0, *hb1, *wpk0, *wpk1;
    cudaGetSymbolAddress((void**)&xg,   g_xg);
    cudaGetSymbolAddress((void**)&ys0,  g_ys0);
    cudaGetSymbolAddress((void**)&ys1,  g_ys1);
    cudaGetSymbolAddress((void**)&hb0,  g_hb0);
    cudaGetSymbolAddress((void**)&hb1,  g_hb1);
    cudaGetSymbolAddress((void**)&wpk0, g_wpk0);
    cudaGetSymbolAddress((void**)&wpk1, g_wpk1);

    cudaFuncSetAttribute(scan16r_kernel, cudaFuncAttributeMaxDynamicSharedMemorySize,
                         S16R_SMEM_BYTES);
    cudaFuncSetAttribute(scan16r_kernel, cudaFuncAttributeNonPortableClusterSizeAllowed, 1);
    cudaFuncSetAttribute(scan8_kernel, cudaFuncAttributeMaxDynamicSharedMemorySize,
                         SCAN8_SMEM_BYTES);

    // runtime capability check: can we launch 16-CTA clusters for scan16r?
    int maxc = 0;
    {
        cudaLaunchConfig_t qcfg = {};
        qcfg.gridDim = dim3(16, 8);
        qcfg.blockDim = dim3(512);
        qcfg.dynamicSmemBytes = S16R_SMEM_BYTES;
        if (cudaOccupancyMaxPotentialClusterSize(&maxc, scan16r_kernel, &qcfg) != cudaSuccess)
            maxc = 0;
    }
    const bool use16 = (maxc >= 16);

    const size_t WSLAB = (size_t)3 * 512 * 512;
    const size_t BSLAB = (size_t)3 * 512;
    const size_t YSSTEP = (size_t)B_SZ * H_SZ;

    dim3 pgrid(12, 512);
    int  pkblocks = (3 * 512 * 512 + 255) / 256;

    if (!use16) {   // fallback needs packed weights
        pack_wh<<<pkblocks, 256>>>(Wh + 0 * WSLAB, wpk0);
        pack_wh<<<pkblocks, 256>>>(Wh + 2 * WSLAB, wpk1);
    }

    auto launch_scan = [&](const float* xgp, const float* whraw, const float* wpkp, float* ysp) {
        if (use16) {
            cudaLaunchConfig_t cfg = {};
            cfg.gridDim = dim3(16, 8);
            cfg.blockDim = dim3(512);
            cfg.dynamicSmemBytes = S16R_SMEM_BYTES;
            cfg.stream = 0;
            cudaLaunchAttribute at[1];
            at[0].id = cudaLaunchAttributeClusterDimension;
            at[0].val.clusterDim.x = 16;
            at[0].val.clusterDim.y = 1;
            at[0].val.clusterDim.z = 1;
            cfg.attrs = at;
            cfg.numAttrs = 1;
            int S = S_SZ;
            cudaLaunchKernelEx(&cfg, scan16r_kernel, xgp, whraw, ysp, S);
        } else {
            scan8_kernel<<<dim3(8, 8), 512, SCAN8_SMEM_BYTES>>>(
                xgp, (const float4*)wpkp, ysp, S_SZ);
        }
    };

    // ---- forward layer 0 ----
    proj_kernel<<<pgrid, 256>>>(x, (long)S_SZ * I_SZ, (long)I_SZ,
                                Wi + 0 * WSLAB, bb + 0 * BSLAB, xg, S_SZ);
    launch_scan(xg, Wh + 0 * WSLAB, wpk0, ys0);

    // ---- forward layer 1 ----
    proj_kernel<<<pgrid, 256>>>(ys0, (long)H_SZ, (long)B_SZ * H_SZ,
                                Wi + 2 * WSLAB, bb + 2 * BSLAB, xg, S_SZ);
    launch_scan(xg, Wh + 2 * WSLAB, wpk1, ys1);

    // ---- backward direction collapses to two single GRU steps (h0 = 0) ----
    dim3 bgrid(4, 64);
    bwd_step<<<bgrid, 128>>>(x, (long)S_SZ * I_SZ, (long)(S_SZ - 1) * I_SZ,
                             Wi + 1 * WSLAB, bb + 1 * BSLAB, hb0);
    bwd_step<<<bgrid, 128>>>(hb0, (long)H_SZ, 0L,
                             Wi + 3 * WSLAB, bb + 3 * BSLAB, hb1);

    // ---- final FC on [out_f[:, -1], out_b[:, -1]] ----
    fc_kernel<<<bgrid, 128>>>(ys1 + (size_t)(S_SZ - 1) * YSSTEP, hb1, fw, fb, out);
}

// round 11
// speedup vs baseline: 1.9060x; 1.6424x over previous
#include <cuda_runtime.h>
#include <math.h>

#define B_SZ 64
#define S_SZ 1024
#define I_SZ 512
#define H_SZ 512

// ---------------- static device scratch (no allocations allowed) ----------------
__device__ float g_xg  [(size_t)S_SZ * 3 * B_SZ * H_SZ];  // [S][3][B][H]
__device__ float g_ys0 [(size_t)S_SZ * B_SZ * H_SZ];      // layer-0 fwd outputs [S][B][H]
__device__ float g_ys1 [(size_t)S_SZ * B_SZ * H_SZ];      // layer-1 fwd outputs
__device__ float g_hb0 [B_SZ * H_SZ];
__device__ float g_hb1 [B_SZ * H_SZ];
__device__ float g_wpk0[3 * 512 * 512];                   // packed Wh layer0 (fallback path)
__device__ float g_wpk1[3 * 512 * 512];                   // packed Wh layer1 (fallback path)
__device__ float g_wf0 [3 * 512 * 512];                   // frag-packed Wh layer0 (tensor path)
__device__ float g_wf1 [3 * 512 * 512];                   // frag-packed Wh layer1 (tensor path)

// ---------------- tf32 helpers ----------------
__device__ __forceinline__ unsigned f2tf(float x) {
    unsigned u;
    asm("cvt.rna.tf32.f32 %0, %1;" : "=r"(u) : "f"(x));
    return u;
}

__device__ __forceinline__ void mma8(float* c, const unsigned* a, unsigned b0, unsigned b1) {
    asm volatile(
        "mma.sync.aligned.m16n8k8.row.col.f32.tf32.tf32.f32 "
        "{%0,%1,%2,%3}, {%4,%5,%6,%7}, {%8,%9}, {%0,%1,%2,%3};"
        : "+f"(c[0]), "+f"(c[1]), "+f"(c[2]), "+f"(c[3])
        : "r"(a[0]), "r"(a[1]), "r"(a[2]), "r"(a[3]), "r"(b0), "r"(b1));
}

// ---------------- projection GEMM (verified working, unchanged) ----------------
__global__ void __launch_bounds__(256) proj_kernel(
    const float* __restrict__ X, long sb, long ss,
    const float* __restrict__ W, const float* __restrict__ bias,
    float* __restrict__ out, int Srows)
{
    __shared__ float As[128][36];
    __shared__ float Bs[32][136];

    const int M  = Srows * B_SZ;
    const int m0 = blockIdx.y * 128;
    const int n0 = blockIdx.x * 128;
    const int g  = n0 >> 9;
    const int h0 = n0 & 511;
    const float* Wg = W + (size_t)g * H_SZ * H_SZ;

    const int tid  = threadIdx.x;
    const int lane = tid & 31;
    const int warp = tid >> 5;
    const int wm   = warp & 3;
    const int wn   = warp >> 2;

    float acc[2][8][4];
#pragma unroll
    for (int i = 0; i < 2; i++)
#pragma unroll
        for (int jf = 0; jf < 8; jf++)
#pragma unroll
            for (int k = 0; k < 4; k++) acc[i][jf][k] = 0.f;

    for (int k0 = 0; k0 < H_SZ; k0 += 32) {
#pragma unroll
        for (int i = 0; i < 4; i++) {
            int idx = tid + i * 256;
            int row = idx >> 3;
            int kk  = (idx & 7) << 2;
            float4 v = make_float4(0.f, 0.f, 0.f, 0.f);
            int r = m0 + row;
            if (r < M) {
                int s = r >> 6, b = r & 63;
                v = *(const float4*)(X + (size_t)b * sb + (size_t)s * ss + k0 + kk);
            }
            As[row][kk + 0] = __uint_as_float(f2tf(v.x));
            As[row][kk + 1] = __uint_as_float(f2tf(v.y));
            As[row][kk + 2] = __uint_as_float(f2tf(v.z));
            As[row][kk + 3] = __uint_as_float(f2tf(v.w));
        }
#pragma unroll
        for (int i = 0; i < 4; i++) {
            int idx = tid + i * 256;
            int kk  = idx >> 5;
            int nn  = (idx & 31) << 2;
            float4 v = *(const float4*)(Wg + (size_t)(k0 + kk) * H_SZ + h0 + nn);
            Bs[kk][nn + 0] = __uint_as_float(f2tf(v.x));
            Bs[kk][nn + 1] = __uint_as_float(f2tf(v.y));
            Bs[kk][nn + 2] = __uint_as_float(f2tf(v.z));
            Bs[kk][nn + 3] = __uint_as_float(f2tf(v.w));
        }
        __syncthreads();

#pragma unroll
        for (int kq = 0; kq < 4; kq++) {
            const int kr = kq * 8;
            unsigned a[2][4];
#pragma unroll
            for (int mf = 0; mf < 2; mf++) {
                int rb = wm * 32 + mf * 16 + (lane >> 2);
                int c  = kr + (lane & 3);
                a[mf][0] = __float_as_uint(As[rb][c]);
                a[mf][1] = __float_as_uint(As[rb + 8][c]);
                a[mf][2] = __float_as_uint(As[rb][c + 4]);
                a[mf][3] = __float_as_uint(As[rb + 8][c + 4]);
            }
#pragma unroll
            for (int nf = 0; nf < 8; nf++) {
                int cb = wn * 64 + nf * 8 + (lane >> 2);
                unsigned b0 = __float_as_uint(Bs[kr + (lane & 3)][cb]);
                unsigned b1 = __float_as_uint(Bs[kr + (lane & 3) + 4][cb]);
                mma8(acc[0][nf], a[0], b0, b1);
                mma8(acc[1][nf], a[1], b0, b1);
            }
        }
        __syncthreads();
    }

#pragma unroll
    for (int mf = 0; mf < 2; mf++) {
#pragma unroll
        for (int nf = 0; nf < 8; nf++) {
            int col = wn * 64 + nf * 8 + ((lane & 3) << 1);
            int h   = h0 + col;
            float b0v = bias[g * H_SZ + h];
            float b1v = bias[g * H_SZ + h + 1];
            int r = m0 + wm * 32 + mf * 16 + (lane >> 2);
            if (r < M) {
                int s = r >> 6, b = r & 63;
                float* o = out + ((size_t)(s * 3 + g) * B_SZ + b) * H_SZ + h;
                o[0] = acc[mf][nf][0] + b0v;
                o[1] = acc[mf][nf][1] + b1v;
            }
            int r2 = r + 8;
            if (r2 < M) {
                int s = r2 >> 6, b = r2 & 63;
                float* o = out + ((size_t)(s * 3 + g) * B_SZ + b) * H_SZ + h;
                o[0] = acc[mf][nf][2] + b0v;
                o[1] = acc[mf][nf][3] + b1v;
            }
        }
    }
}

// ---------------- Wh pre-pack for fallback scan8 ----------------
__global__ void __launch_bounds__(256) pack_wh(const float* __restrict__ Wh,
                                               float* __restrict__ wpk)
{
    int idx = blockIdx.x * 256 + threadIdx.x;
    if (idx < 3 * 512 * 512) {
        int col = idx & 511;
        int k   = (idx >> 9) & 511;
        int g   = idx >> 18;
        wpk[((((size_t)g * 128 + (k >> 2)) * 512 + col) << 2) + (k & 3)] = Wh[idx];
    }
}

// ---------------- Wh frag-pack for tensor scan ----------------
// pair p = (((g*16 + cg)*4 + nf)*64 + kt)*32 + lane holds
//   b0 = tf32(Wh[g][kt*8 + (lane&3)    ][cg*32 + nf*8 + (lane>>2)])
//   b1 = tf32(Wh[g][kt*8 + (lane&3) + 4][same col])
// TOTAL pairs = 3*16*4*64*32 = 393216  (round-10 bug: only half were packed)
#define FRAG_PAIRS 393216
__global__ void __launch_bounds__(256) pack_frag(const float* __restrict__ Wh,
                                                 float* __restrict__ wf)
{
    int p = blockIdx.x * 256 + threadIdx.x;
    if (p < FRAG_PAIRS) {
        int lane = p & 31;
        int kt   = (p >> 5) & 63;
        int nf   = (p >> 11) & 3;
        int cg   = (p >> 13) & 15;
        int g    = p >> 17;
        int col  = cg * 32 + nf * 8 + (lane >> 2);
        int k    = kt * 8 + (lane & 3);
        wf[2 * p + 0] = __uint_as_float(f2tf(Wh[((size_t)g * 512 + k) * 512 + col]));
        wf[2 * p + 1] = __uint_as_float(f2tf(Wh[((size_t)g * 512 + k + 4) * 512 + col]));
    }
}

// ================= PRIMARY scan: tensor-core mma, cluster-16 =================
// grid (16, 4): x = colgroup (32 cols), y = bgrp (16 batches). Cluster 16 along x.
// 512 threads: warps 0-11 do mma (kc = w&3 K-slice of 128, g = w>>2 gate);
// warps 12-15 help stage/gate only. Gates 0,1 weight frags in smem; gate 2 LDG-streamed.
// A = h [16x512] split hi/lo tf32 (2 mma into same fp32 acc => ~fp32-exact h).
#define HS_STRIDE 516
#define SM_WSM   0
#define SM_HSHI  32768
#define SM_HSLO  (32768 + 16 * HS_STRIDE)
#define SM_RED   (32768 + 32 * HS_STRIDE)
#define S16T_SMEM_FLOATS (SM_RED + 4 * 16 * 100)
#define S16T_SMEM_BYTES  (S16T_SMEM_FLOATS * 4)   // 222720 B

template <bool STREAM>
__device__ __forceinline__ void matvec_part(
    const float* __restrict__ sm, const float* __restrict__ wsmg,
    const unsigned long long* __restrict__ wfg, int ktb, int lane, float c[4][4])
{
    const int rb  = lane >> 2;
    const int kap = lane & 3;
#pragma unroll 4
    for (int kt = 0; kt < 16; kt++) {
        const int k0 = (ktb + kt) << 3;
        const int ab = rb * HS_STRIDE + k0 + kap;
        unsigned ah[4], al[4];
        ah[0] = __float_as_uint(sm[SM_HSHI + ab]);
        ah[1] = __float_as_uint(sm[SM_HSHI + ab + 8 * HS_STRIDE]);
        ah[2] = __float_as_uint(sm[SM_HSHI + ab + 4]);
        ah[3] = __float_as_uint(sm[SM_HSHI + ab + 8 * HS_STRIDE + 4]);
        al[0] = __float_as_uint(sm[SM_HSLO + ab]);
        al[1] = __float_as_uint(sm[SM_HSLO + ab + 8 * HS_STRIDE]);
        al[2] = __float_as_uint(sm[SM_HSLO + ab + 4]);
        al[3] = __float_as_uint(sm[SM_HSLO + ab + 8 * HS_STRIDE + 4]);
#pragma unroll
        for (int nf = 0; nf < 4; nf++) {
            unsigned long long bv;
            if (STREAM)
                bv = __ldg(wfg + nf * 2048 + (ktb + kt) * 32 + lane);
            else
                bv = *(const unsigned long long*)(wsmg + nf * 4096 + (ktb + kt) * 64 + lane * 2);
            mma8(c[nf], ah, (unsigned)bv, (unsigned)(bv >> 32));
            mma8(c[nf], al, (unsigned)bv, (unsigned)(bv >> 32));
        }
    }
}

__global__ void __launch_bounds__(512, 1)
scan16t_kernel(const float* __restrict__ xg,   // [S][3][B][H]
               const float* __restrict__ wf,   // frag-packed Wh (this layer)
               float* __restrict__ ys,         // [S][B][H]
               int S)
{
    extern __shared__ float sm[];

    const int tid  = threadIdx.x;
    const int lane = tid & 31;
    const int w    = tid >> 5;
    const int kc   = w & 3;          // mma warps: K-slice
    const int g    = w >> 2;         // mma warps: gate (0..2); w>=12 -> inactive
    const int cg   = blockIdx.x;     // 0..15 colgroup
    const int j0   = cg << 5;
    const int b0   = blockIdx.y << 4; // 16 batches

    // one-time: copy gate 0,1 frag slices into smem (each 16384 floats, contiguous)
    {
        const float4* src = (const float4*)(wf);
        float4*       dst = (float4*)(sm + SM_WSM);
#pragma unroll
        for (int gg = 0; gg < 2; gg++) {
            const float4* s4 = src + (size_t)(gg * 16 + cg) * 4096;
            float4*       d4 = dst + gg * 4096;
            for (int i = tid; i < 4096; i += 512) d4[i] = s4[i];
        }
    }

    const float* wsmg = sm + SM_WSM + (g < 2 ? g * 16384 : 0);
    const unsigned long long* wfg =
        (const unsigned long long*)wf + ((size_t)(2 * 16 + cg) * 4) * 2048;

    const int gb = tid >> 5;   // gate-stage batch (0..15)
    const int gj = tid & 31;   // gate-stage col   (0..31)

    for (int s = 0; s < S; s++) {
        // prefetch gate operands + exact h_prev for this thread's output
        float x0, x1, x2, hprev;
        {
            const size_t xb = ((size_t)(s * 3 + 0) * B_SZ + b0 + gb) * H_SZ + j0 + gj;
            x0 = __ldg(xg + xb);
            x1 = __ldg(xg + xb + (size_t)B_SZ * H_SZ);
            x2 = __ldg(xg + xb + (size_t)2 * B_SZ * H_SZ);
            hprev = (s == 0) ? 0.f
                : __ldcg(ys + ((size_t)(s - 1) * B_SZ + b0 + gb) * H_SZ + j0 + gj);
        }

        // stage h_prev [16][512] as hi/lo tf32 planes (coalesced)
        if (s == 0) {
            float4 z = make_float4(0.f, 0.f, 0.f, 0.f);
            for (int i = tid; i < 2 * 16 * 129; i += 512)
                ((float4*)(sm + SM_HSHI))[i] = z;
        } else {
#pragma unroll
            for (int it = 0; it < 4; it++) {
                int i  = tid + it * 512;     // 0..2047
                int b  = i >> 7;
                int k4 = i & 127;
                float4 v = __ldcg((const float4*)(ys + ((size_t)(s - 1) * B_SZ + b0 + b) * H_SZ) + k4);
                float4 hi, lo;
                hi.x = __uint_as_float(f2tf(v.x)); lo.x = __uint_as_float(f2tf(v.x - hi.x));
                hi.y = __uint_as_float(f2tf(v.y)); lo.y = __uint_as_float(f2tf(v.y - hi.y));
                hi.z = __uint_as_float(f2tf(v.z)); lo.z = __uint_as_float(f2tf(v.z - hi.z));
                hi.w = __uint_as_float(f2tf(v.w)); lo.w = __uint_as_float(f2tf(v.w - hi.w));
                *(float4*)&sm[SM_HSHI + b * HS_STRIDE + (k4 << 2)] = hi;
                *(float4*)&sm[SM_HSLO + b * HS_STRIDE + (k4 << 2)] = lo;
            }
        }
        __syncthreads();

        // tensor matvec (warps 0-11)
        if (w < 12) {
            float c[4][4];
#pragma unroll
            for (int nf = 0; nf < 4; nf++)
#pragma unroll
                for (int q = 0; q < 4; q++) c[nf][q] = 0.f;

            if (g < 2) matvec_part<false>(sm, wsmg, wfg, kc * 16, lane, c);
            else       matvec_part<true >(sm, wsmg, wfg, kc * 16, lane, c);

            // store c-frags to red[kc][row][gate*32 + col]
#pragma unroll
            for (int nf = 0; nf < 4; nf++) {
                int gcol = (g << 5) + (nf << 3) + ((lane & 3) << 1);
                int row  = lane >> 2;
                float2 p01 = make_float2(c[nf][0], c[nf][1]);
                float2 p23 = make_float2(c[nf][2], c[nf][3]);
                *(float2*)&sm[SM_RED + kc * 1600 + row * 100 + gcol]       = p01;
                *(float2*)&sm[SM_RED + kc * 1600 + (row + 8) * 100 + gcol] = p23;
            }
        }
        __syncthreads();

        // gate stage: 512 threads, one per (batch gb, col gj)
        {
            float s0 = 0.f, s1 = 0.f, s2 = 0.f;
#pragma unroll
            for (int c8 = 0; c8 < 4; c8++) {
                s0 += sm[SM_RED + c8 * 1600 + gb * 100 +      gj];
                s1 += sm[SM_RED + c8 * 1600 + gb * 100 + 32 + gj];
                s2 += sm[SM_RED + c8 * 1600 + gb * 100 + 64 + gj];
            }
            float r  = 1.f / (1.f + expf(-(x0 + s0)));
            float z  = 1.f / (1.f + expf(-(x1 + s1)));
            float n  = tanhf(x2 + r * s2);
            float hn = (1.f - z) * n + z * hprev;
            ys[((size_t)s * B_SZ + b0 + gb) * H_SZ + j0 + gj] = hn;
        }

        asm volatile("barrier.cluster.arrive.aligned;" ::: "memory");
        asm volatile("barrier.cluster.wait.aligned;"   ::: "memory");
    }
}

// ================= FALLBACK scan: exact round-6 kernel (cluster 8) =================
#define SCAN8_SMEM_BYTES ((4096 + 12288) * 4)

__global__ void __launch_bounds__(512, 1) __cluster_dims__(8, 1, 1)
scan8_kernel(const float* __restrict__ xg, const float4* __restrict__ wpk,
             float* __restrict__ ys, int S)
{
    extern __shared__ float sm[];
    float*  hs  = sm;
    float*  red = sm + 4096;
    float4* hs4 = (float4*)hs;

    const int tid  = threadIdx.x;
    const int lane = tid & 31;
    const int w    = tid >> 5;
    const int kc   = w >> 1;
    const int jh   = w & 1;
    const int j0   = blockIdx.x << 6;
    const int b0   = blockIdx.y << 3;
    const int col  = j0 + (jh << 5) + lane;
    const int k4b  = kc << 4;
    const int jc   = (jh << 5) + lane;

    const int gb = tid >> 6;
    const int gj = tid & 63;

    const float4* w0p = wpk + ((size_t)(0 * 128 + k4b) << 9) + col;
    const float4* w1p = wpk + ((size_t)(1 * 128 + k4b) << 9) + col;
    const float4* w2p = wpk + ((size_t)(2 * 128 + k4b) << 9) + col;

    for (int s = 0; s < S; s++) {
        if (s == 0) {
            for (int i = tid; i < 1024; i += 512) hs4[i] = make_float4(0.f, 0.f, 0.f, 0.f);
        } else {
            const float4* hp = (const float4*)(ys + ((size_t)(s - 1) * B_SZ + b0) * H_SZ);
            for (int i = tid; i < 1024; i += 512) hs4[i] = __ldcg(hp + i);
        }
        __syncthreads();

        float acc[3][8];
#pragma unroll
        for (int g = 0; g < 3; g++)
#pragma unroll
            for (int b = 0; b < 8; b++) acc[g][b] = 0.f;

#pragma unroll 4
        for (int t = 0; t < 16; t++) {
            float4 w0 = __ldg(w0p + ((size_t)t << 9));
            float4 w1 = __ldg(w1p + ((size_t)t << 9));
            float4 w2 = __ldg(w2p + ((size_t)t << 9));
            const int k4 = k4b + t;
#pragma unroll
            for (int b = 0; b < 8; b++) {
                float4 h4 = hs4[b * 128 + k4];
                acc[0][b] += h4.x * w0.x + h4.y * w0.y + h4.z * w0.z + h4.w * w0.w;
                acc[1][b] += h4.x * w1.x + h4.y * w1.y + h4.z * w1.z + h4.w * w1.w;
                acc[2][b] += h4.x * w2.x + h4.y * w2.y + h4.z * w2.z + h4.w * w2.w;
            }
        }

#pragma unroll
        for (int g = 0; g < 3; g++)
#pragma unroll
            for (int b = 0; b < 8; b++)
                red[((kc * 3 + g) * 8 + b) * 64 + jc] = acc[g][b];
        __syncthreads();

        float a0 = 0.f, a1 = 0.f, a2 = 0.f;
#pragma unroll
        for (int c = 0; c < 8; c++) {
            a0 += red[((c * 3 + 0) * 8 + gb) * 64 + gj];
            a1 += red[((c * 3 + 1) * 8 + gb) * 64 + gj];
            a2 += red[((c * 3 + 2) * 8 + gb) * 64 + gj];
        }

        float hprev = hs[gb * 512 + j0 + gj];

        const size_t xi = ((size_t)s * 3 * B_SZ + (b0 + gb)) * H_SZ + j0 + gj;
        float x0 = xg[xi];
        float x1 = xg[xi + (size_t)B_SZ * H_SZ];
        float x2 = xg[xi + (size_t)2 * B_SZ * H_SZ];

        float r  = 1.f / (1.f + expf(-(x0 + a0)));
        float z  = 1.f / (1.f + expf(-(x1 + a1)));
        float n  = tanhf(x2 + r * a2);
        float hn = (1.f - z) * n + z * hprev;

        ys[((size_t)s * B_SZ + b0 + gb) * H_SZ + j0 + gj] = hn;

        asm volatile("barrier.cluster.arrive.aligned;" ::: "memory");
        asm volatile("barrier.cluster.wait.aligned;"   ::: "memory");
    }
}

// ---------------- backward shortcut + final FC (unchanged) ----------------
__global__ void __launch_bounds__(128) bwd_step(
    const float* __restrict__ xin, long bstride, long off,
    const float* __restrict__ Wi, const float* __restrict__ bias,
    float* __restrict__ hout)
{
    int h = blockIdx.x * 128 + threadIdx.x;
    int b = blockIdx.y;
    const float* xr = xin + (size_t)b * bstride + off;
    const float* W1 = Wi + (size_t)1 * 512 * 512 + h;
    const float* W2 = Wi + (size_t)2 * 512 * 512 + h;
    float a1 = 0.f, a2 = 0.f;
    for (int k = 0; k < 512; k++) {
        float xv = __ldg(xr + k);
        a1 += xv * W1[(size_t)k * 512];
        a2 += xv * W2[(size_t)k * 512];
    }
    float z = 1.f / (1.f + expf(-(a1 + bias[512 + h])));
    float n = tanhf(a2 + bias[1024 + h]);
    hout[(size_t)b * 512 + h] = (1.f - z) * n;
}

__global__ void __launch_bounds__(128) fc_kernel(
    const float* __restrict__ ysl, const float* __restrict__ hb,
    const float* __restrict__ fw, const float* __restrict__ fb,
    float* __restrict__ out)
{
    int o = blockIdx.x * 128 + threadIdx.x;
    int b = blockIdx.y;
    float acc = fb[o];
    const float* f0 = ysl + (size_t)b * 512;
    const float* h0 = hb  + (size_t)b * 512;
    for (int jq = 0; jq < 512; jq++) acc += f0[jq] * fw[(size_t)jq * 512 + o];
    for (int jq = 0; jq < 512; jq++) acc += h0[jq] * fw[(size_t)(512 + jq) * 512 + o];
    out[(size_t)b * 512 + o] = acc;
}

// ---------------- launch ----------------
extern "C" void kernel_launch(void* const* d_in, const int* in_sizes, int n_in,
                              void* d_out, int out_size)
{
    (void)in_sizes; (void)n_in; (void)out_size;
    const float* x  = (const float*)d_in[0];
    const float* Wi = (const float*)d_in[1];
    const float* Wh = (const float*)d_in[2];
    const float* bb = (const float*)d_in[3];
    const float* fw = (const float*)d_in[4];
    const float* fb = (const float*)d_in[5];
    float* out = (float*)d_out;

    float *xg, *ys0, *ys1, *hb0, *hb1, *wpk0, *wpk1, *wf0, *wf1;
    cudaGetSymbolAddress((void**)&xg,   g_xg);
    cudaGetSymbolAddress((void**)&ys0,  g_ys0);
    cudaGetSymbolAddress((void**)&ys1,  g_ys1);
    cudaGetSymbolAddress((void**)&hb0,  g_hb0);
    cudaGetSymbolAddress((void**)&hb1,  g_hb1);
    cudaGetSymbolAddress((void**)&wpk0, g_wpk0);
    cudaGetSymbolAddress((void**)&wpk1, g_wpk1);
    cudaGetSymbolAddress((void**)&wf0,  g_wf0);
    cudaGetSymbolAddress((void**)&wf1,  g_wf1);

    cudaFuncSetAttribute(scan16t_kernel, cudaFuncAttributeMaxDynamicSharedMemorySize,
                         S16T_SMEM_BYTES);
    cudaFuncSetAttribute(scan16t_kernel, cudaFuncAttributeNonPortableClusterSizeAllowed, 1);
    cudaFuncSetAttribute(scan8_kernel, cudaFuncAttributeMaxDynamicSharedMemorySize,
                         SCAN8_SMEM_BYTES);

    int maxc = 0;
    {
        cudaLaunchConfig_t qcfg = {};
        qcfg.gridDim = dim3(16, 4);
        qcfg.blockDim = dim3(512);
        qcfg.dynamicSmemBytes = S16T_SMEM_BYTES;
        if (cudaOccupancyMaxPotentialClusterSize(&maxc, scan16t_kernel, &qcfg) != cudaSuccess)
            maxc = 0;
    }
    const bool use16 = (maxc >= 16);

    const size_t WSLAB = (size_t)3 * 512 * 512;
    const size_t BSLAB = (size_t)3 * 512;
    const size_t YSSTEP = (size_t)B_SZ * H_SZ;

    dim3 pgrid(12, 512);
    int  pkblocks = (3 * 512 * 512 + 255) / 256;

    if (use16) {
        pack_frag<<<(FRAG_PAIRS + 255) / 256, 256>>>(Wh + 0 * WSLAB, wf0);
        pack_frag<<<(FRAG_PAIRS + 255) / 256, 256>>>(Wh + 2 * WSLAB, wf1);
    } else {
        pack_wh<<<pkblocks, 256>>>(Wh + 0 * WSLAB, wpk0);
        pack_wh<<<pkblocks, 256>>>(Wh + 2 * WSLAB, wpk1);
    }

    auto launch_scan = [&](const float* xgp, const float* wfp, const float* wpkp, float* ysp) {
        if (use16) {
            cudaLaunchConfig_t cfg = {};
            cfg.gridDim = dim3(16, 4);
            cfg.blockDim = dim3(512);
            cfg.dynamicSmemBytes = S16T_SMEM_BYTES;
            cfg.stream = 0;
            cudaLaunchAttribute at[1];
            at[0].id = cudaLaunchAttributeClusterDimension;
            at[0].val.clusterDim.x = 16;
            at[0].val.clusterDim.y = 1;
            at[0].val.clusterDim.z = 1;
            cfg.attrs = at;
            cfg.numAttrs = 1;
            int S = S_SZ;
            cudaLaunchKernelEx(&cfg, scan16t_kernel, xgp, wfp, ysp, S);
        } else {
            scan8_kernel<<<dim3(8, 8), 512, SCAN8_SMEM_BYTES>>>(
                xgp, (const float4*)wpkp, ysp, S_SZ);
        }
    };

    proj_kernel<<<pgrid, 256>>>(x, (long)S_SZ * I_SZ, (long)I_SZ,
                                Wi + 0 * WSLAB, bb + 0 * BSLAB, xg, S_SZ);
    launch_scan(xg, wf0, wpk0, ys0);

    proj_kernel<<<pgrid, 256>>>(ys0, (long)H_SZ, (long)B_SZ * H_SZ,
                                Wi + 2 * WSLAB, bb + 2 * BSLAB, xg, S_SZ);
    launch_scan(xg, wf1, wpk1, ys1);

    dim3 bgrid(4, 64);
    bwd_step<<<bgrid, 128>>>(x, (long)S_SZ * I_SZ, (long)(S_SZ - 1) * I_SZ,
                             Wi + 1 * WSLAB, bb + 1 * BSLAB, hb0);
    bwd_step<<<bgrid, 128>>>(hb0, (long)H_SZ, 0L,
                             Wi + 3 * WSLAB, bb + 3 * BSLAB, hb1);

    fc_kernel<<<bgrid, 128>>>(ys1 + (size_t)(S_SZ - 1) * YSSTEP, hb1, fw, fb, out);
}

// round 12
// speedup vs baseline: 2.2588x; 1.1851x over previous
#include <cuda_runtime.h>
#include <math.h>

#define B_SZ 64
#define S_SZ 1024
#define I_SZ 512
#define H_SZ 512

// ---------------- static device scratch (no allocations allowed) ----------------
__device__ float g_xg  [(size_t)S_SZ * 3 * B_SZ * H_SZ];  // [S][3][B][H]
__device__ float g_ys0 [(size_t)S_SZ * B_SZ * H_SZ];      // layer-0 fwd outputs [S][B][H]
__device__ float g_ys1 [(size_t)S_SZ * B_SZ * H_SZ];      // layer-1 fwd outputs
__device__ float g_hb0 [B_SZ * H_SZ];
__device__ float g_hb1 [B_SZ * H_SZ];
__device__ float g_wpk0[3 * 512 * 512];                   // packed Wh layer0 (fallback path)
__device__ float g_wpk1[3 * 512 * 512];                   // packed Wh layer1 (fallback path)
__device__ float g_wf0 [3 * 512 * 512];                   // frag-packed Wh layer0 (tensor path)
__device__ float g_wf1 [3 * 512 * 512];                   // frag-packed Wh layer1 (tensor path)

// ---------------- tf32 helpers ----------------
__device__ __forceinline__ unsigned f2tf(float x) {
    unsigned u;
    asm("cvt.rna.tf32.f32 %0, %1;" : "=r"(u) : "f"(x));
    return u;
}

__device__ __forceinline__ void mma8(float* c, const unsigned* a, unsigned b0, unsigned b1) {
    asm volatile(
        "mma.sync.aligned.m16n8k8.row.col.f32.tf32.tf32.f32 "
        "{%0,%1,%2,%3}, {%4,%5,%6,%7}, {%8,%9}, {%0,%1,%2,%3};"
        : "+f"(c[0]), "+f"(c[1]), "+f"(c[2]), "+f"(c[3])
        : "r"(a[0]), "r"(a[1]), "r"(a[2]), "r"(a[3]), "r"(b0), "r"(b1));
}

// ---------------- projection GEMM (verified working, unchanged) ----------------
__global__ void __launch_bounds__(256) proj_kernel(
    const float* __restrict__ X, long sb, long ss,
    const float* __restrict__ W, const float* __restrict__ bias,
    float* __restrict__ out, int Srows)
{
    __shared__ float As[128][36];
    __shared__ float Bs[32][136];

    const int M  = Srows * B_SZ;
    const int m0 = blockIdx.y * 128;
    const int n0 = blockIdx.x * 128;
    const int g  = n0 >> 9;
    const int h0 = n0 & 511;
    const float* Wg = W + (size_t)g * H_SZ * H_SZ;

    const int tid  = threadIdx.x;
    const int lane = tid & 31;
    const int warp = tid >> 5;
    const int wm   = warp & 3;
    const int wn   = warp >> 2;

    float acc[2][8][4];
#pragma unroll
    for (int i = 0; i < 2; i++)
#pragma unroll
        for (int jf = 0; jf < 8; jf++)
#pragma unroll
            for (int k = 0; k < 4; k++) acc[i][jf][k] = 0.f;

    for (int k0 = 0; k0 < H_SZ; k0 += 32) {
#pragma unroll
        for (int i = 0; i < 4; i++) {
            int idx = tid + i * 256;
            int row = idx >> 3;
            int kk  = (idx & 7) << 2;
            float4 v = make_float4(0.f, 0.f, 0.f, 0.f);
            int r = m0 + row;
            if (r < M) {
                int s = r >> 6, b = r & 63;
                v = *(const float4*)(X + (size_t)b * sb + (size_t)s * ss + k0 + kk);
            }
            As[row][kk + 0] = __uint_as_float(f2tf(v.x));
            As[row][kk + 1] = __uint_as_float(f2tf(v.y));
            As[row][kk + 2] = __uint_as_float(f2tf(v.z));
            As[row][kk + 3] = __uint_as_float(f2tf(v.w));
        }
#pragma unroll
        for (int i = 0; i < 4; i++) {
            int idx = tid + i * 256;
            int kk  = idx >> 5;
            int nn  = (idx & 31) << 2;
            float4 v = *(const float4*)(Wg + (size_t)(k0 + kk) * H_SZ + h0 + nn);
            Bs[kk][nn + 0] = __uint_as_float(f2tf(v.x));
            Bs[kk][nn + 1] = __uint_as_float(f2tf(v.y));
            Bs[kk][nn + 2] = __uint_as_float(f2tf(v.z));
            Bs[kk][nn + 3] = __uint_as_float(f2tf(v.w));
        }
        __syncthreads();

#pragma unroll
        for (int kq = 0; kq < 4; kq++) {
            const int kr = kq * 8;
            unsigned a[2][4];
#pragma unroll
            for (int mf = 0; mf < 2; mf++) {
                int rb = wm * 32 + mf * 16 + (lane >> 2);
                int c  = kr + (lane & 3);
                a[mf][0] = __float_as_uint(As[rb][c]);
                a[mf][1] = __float_as_uint(As[rb + 8][c]);
                a[mf][2] = __float_as_uint(As[rb][c + 4]);
                a[mf][3] = __float_as_uint(As[rb + 8][c + 4]);
            }
#pragma unroll
            for (int nf = 0; nf < 8; nf++) {
                int cb = wn * 64 + nf * 8 + (lane >> 2);
                unsigned b0 = __float_as_uint(Bs[kr + (lane & 3)][cb]);
                unsigned b1 = __float_as_uint(Bs[kr + (lane & 3) + 4][cb]);
                mma8(acc[0][nf], a[0], b0, b1);
                mma8(acc[1][nf], a[1], b0, b1);
            }
        }
        __syncthreads();
    }

#pragma unroll
    for (int mf = 0; mf < 2; mf++) {
#pragma unroll
        for (int nf = 0; nf < 8; nf++) {
            int col = wn * 64 + nf * 8 + ((lane & 3) << 1);
            int h   = h0 + col;
            float b0v = bias[g * H_SZ + h];
            float b1v = bias[g * H_SZ + h + 1];
            int r = m0 + wm * 32 + mf * 16 + (lane >> 2);
            if (r < M) {
                int s = r >> 6, b = r & 63;
                float* o = out + ((size_t)(s * 3 + g) * B_SZ + b) * H_SZ + h;
                o[0] = acc[mf][nf][0] + b0v;
                o[1] = acc[mf][nf][1] + b1v;
            }
            int r2 = r + 8;
            if (r2 < M) {
                int s = r2 >> 6, b = r2 & 63;
                float* o = out + ((size_t)(s * 3 + g) * B_SZ + b) * H_SZ + h;
                o[0] = acc[mf][nf][2] + b0v;
                o[1] = acc[mf][nf][3] + b1v;
            }
        }
    }
}

// ---------------- Wh pre-pack for fallback scan8 ----------------
__global__ void __launch_bounds__(256) pack_wh(const float* __restrict__ Wh,
                                               float* __restrict__ wpk)
{
    int idx = blockIdx.x * 256 + threadIdx.x;
    if (idx < 3 * 512 * 512) {
        int col = idx & 511;
        int k   = (idx >> 9) & 511;
        int g   = idx >> 18;
        wpk[((((size_t)g * 128 + (k >> 2)) * 512 + col) << 2) + (k & 3)] = Wh[idx];
    }
}

// ---------------- Wh frag-pack for tensor scan (verified round 11) ----------------
#define FRAG_PAIRS 393216
__global__ void __launch_bounds__(256) pack_frag(const float* __restrict__ Wh,
                                                 float* __restrict__ wf)
{
    int p = blockIdx.x * 256 + threadIdx.x;
    if (p < FRAG_PAIRS) {
        int lane = p & 31;
        int kt   = (p >> 5) & 63;
        int nf   = (p >> 11) & 3;
        int cg   = (p >> 13) & 15;
        int g    = p >> 17;
        int col  = cg * 32 + nf * 8 + (lane >> 2);
        int k    = kt * 8 + (lane & 3);
        wf[2 * p + 0] = __uint_as_float(f2tf(Wh[((size_t)g * 512 + k) * 512 + col]));
        wf[2 * p + 1] = __uint_as_float(f2tf(Wh[((size_t)g * 512 + k + 4) * 512 + col]));
    }
}

// ================= PRIMARY scan: tensor-core mma, cluster-16, single tf32 plane =================
// grid (16, 4): x = colgroup (32 cols), y = bgrp (16 batches). Cluster 16 along x.
// Warps 0-11 mma (kc = w&3 K-slice, g = w>>2 gate). Gates 0,1 fully in smem;
// gate 2: first 9 kt of each k-slice cached in smem (36KB), remaining 7 streamed from L2.
#define W2_KT    9
#define HS_STRIDE 516
#define SM_WSM   0
#define SM_W2    32768
#define SM_HSHI  (32768 + 4 * W2_KT * 4 * 32 * 2)     // 41984
#define SM_RED   (SM_HSHI + 16 * HS_STRIDE)           // 50240
#define S16T_SMEM_FLOATS (SM_RED + 4 * 16 * 100)      // 56640
#define S16T_SMEM_BYTES  (S16T_SMEM_FLOATS * 4)       // 226560 B

// MODE 0: weights fully in smem (gates 0,1). MODE 1: gate 2 mixed smem/L2.
template <int MODE>
__device__ __forceinline__ void matvec_part(
    const float* __restrict__ sm, const float* __restrict__ wsmg,
    const unsigned long long* __restrict__ w2sm,   // MODE1: smem base incl. lane
    const unsigned long long* __restrict__ wfgkc,  // MODE1: L2 base incl. kc,lane
    int ktb, int lane, float c[4][4])
{
    const int rb  = lane >> 2;
    const int kap = lane & 3;
#pragma unroll 4
    for (int kt = 0; kt < 16; kt++) {
        const int k0 = (ktb + kt) << 3;
        const int ab = rb * HS_STRIDE + k0 + kap;
        unsigned ah[4];
        ah[0] = __float_as_uint(sm[SM_HSHI + ab]);
        ah[1] = __float_as_uint(sm[SM_HSHI + ab + 8 * HS_STRIDE]);
        ah[2] = __float_as_uint(sm[SM_HSHI + ab + 4]);
        ah[3] = __float_as_uint(sm[SM_HSHI + ab + 8 * HS_STRIDE + 4]);
#pragma unroll
        for (int nf = 0; nf < 4; nf++) {
            unsigned long long bv;
            if (MODE == 0)
                bv = *(const unsigned long long*)(wsmg + nf * 4096 + (ktb + kt) * 64 + lane * 2);
            else if (kt < W2_KT)
                bv = w2sm[(kt * 4 + nf) * 32];
            else
                bv = __ldg(wfgkc + nf * 2048 + kt * 32);
            mma8(c[nf], ah, (unsigned)bv, (unsigned)(bv >> 32));
        }
    }
}

__global__ void __launch_bounds__(512, 1)
scan16t_kernel(const float* __restrict__ xg,   // [S][3][B][H]
               const float* __restrict__ wf,   // frag-packed Wh (this layer)
               float* __restrict__ ys,         // [S][B][H]
               int S)
{
    extern __shared__ float sm[];

    const int tid  = threadIdx.x;
    const int lane = tid & 31;
    const int w    = tid >> 5;
    const int kc   = w & 3;           // mma warps: K-slice
    const int g    = w >> 2;          // mma warps: gate (0..2); w>=12 -> inactive
    const int cg   = blockIdx.x;      // 0..15 colgroup
    const int j0   = cg << 5;
    const int b0   = blockIdx.y << 4; // 16 batches

    // one-time: gates 0,1 frag slices into smem (each 16384 floats, contiguous)
    {
        const float4* src = (const float4*)(wf);
        float4*       dst = (float4*)(sm + SM_WSM);
#pragma unroll
        for (int gg = 0; gg < 2; gg++) {
            const float4* s4 = src + (size_t)(gg * 16 + cg) * 4096;
            float4*       d4 = dst + gg * 4096;
            for (int i = tid; i < 4096; i += 512) d4[i] = s4[i];
        }
    }

    const unsigned long long* wfg =
        (const unsigned long long*)wf + ((size_t)(2 * 16 + cg) * 4) * 2048;

    // one-time: gate-2 partial cache: [kc][t<W2_KT][nf][lane]
    {
        unsigned long long* w2 = (unsigned long long*)(sm + SM_W2);
        for (int i = tid; i < 4 * W2_KT * 4 * 32; i += 512) {
            int ln = i & 31;
            int nf = (i >> 5) & 3;
            int r  = i >> 7;           // kc*W2_KT + t
            int kcc = r / W2_KT;
            int t   = r % W2_KT;
            w2[i] = wfg[nf * 2048 + (kcc * 16 + t) * 32 + ln];
        }
    }

    const float* wsmg = sm + SM_WSM + (g < 2 ? g * 16384 : 0);
    const unsigned long long* w2sm =
        (const unsigned long long*)(sm + SM_W2) + (kc * W2_KT * 4) * 32 + lane;
    const unsigned long long* wfgkc = wfg + (kc * 16) * 32 + lane;

    const int gb = tid >> 5;   // gate-stage batch (0..15)
    const int gj = tid & 31;   // gate-stage col   (0..31)

    for (int s = 0; s < S; s++) {
        // prefetch gate operands + exact h_prev for this thread's output
        float x0, x1, x2, hprev;
        {
            const size_t xb = ((size_t)(s * 3 + 0) * B_SZ + b0 + gb) * H_SZ + j0 + gj;
            x0 = __ldg(xg + xb);
            x1 = __ldg(xg + xb + (size_t)B_SZ * H_SZ);
            x2 = __ldg(xg + xb + (size_t)2 * B_SZ * H_SZ);
            hprev = (s == 0) ? 0.f
                : __ldcg(ys + ((size_t)(s - 1) * B_SZ + b0 + gb) * H_SZ + j0 + gj);
        }

        // stage h_prev [16][512] as single tf32 plane (coalesced)
        if (s == 0) {
            float4 z = make_float4(0.f, 0.f, 0.f, 0.f);
            for (int i = tid; i < 16 * 129; i += 512)
                ((float4*)(sm + SM_HSHI))[i] = z;
        } else {
#pragma unroll
            for (int it = 0; it < 4; it++) {
                int i  = tid + it * 512;     // 0..2047
                int b  = i >> 7;
                int k4 = i & 127;
                float4 v = __ldcg((const float4*)(ys + ((size_t)(s - 1) * B_SZ + b0 + b) * H_SZ) + k4);
                float4 hi;
                hi.x = __uint_as_float(f2tf(v.x));
                hi.y = __uint_as_float(f2tf(v.y));
                hi.z = __uint_as_float(f2tf(v.z));
                hi.w = __uint_as_float(f2tf(v.w));
                *(float4*)&sm[SM_HSHI + b * HS_STRIDE + (k4 << 2)] = hi;
            }
        }
        __syncthreads();

        // tensor matvec (warps 0-11)
        if (w < 12) {
            float c[4][4];
#pragma unroll
            for (int nf = 0; nf < 4; nf++)
#pragma unroll
                for (int q = 0; q < 4; q++) c[nf][q] = 0.f;

            if (g < 2) matvec_part<0>(sm, wsmg, w2sm, wfgkc, kc * 16, lane, c);
            else       matvec_part<1>(sm, wsmg, w2sm, wfgkc, kc * 16, lane, c);

            // store c-frags to red[kc][row][gate*32 + col]
#pragma unroll
            for (int nf = 0; nf < 4; nf++) {
                int gcol = (g << 5) + (nf << 3) + ((lane & 3) << 1);
                int row  = lane >> 2;
                float2 p01 = make_float2(c[nf][0], c[nf][1]);
                float2 p23 = make_float2(c[nf][2], c[nf][3]);
                *(float2*)&sm[SM_RED + kc * 1600 + row * 100 + gcol]       = p01;
                *(float2*)&sm[SM_RED + kc * 1600 + (row + 8) * 100 + gcol] = p23;
            }
        }
        __syncthreads();

        // gate stage: 512 threads, one per (batch gb, col gj)
        {
            float s0 = 0.f, s1 = 0.f, s2 = 0.f;
#pragma unroll
            for (int c8 = 0; c8 < 4; c8++) {
                s0 += sm[SM_RED + c8 * 1600 + gb * 100 +      gj];
                s1 += sm[SM_RED + c8 * 1600 + gb * 100 + 32 + gj];
                s2 += sm[SM_RED + c8 * 1600 + gb * 100 + 64 + gj];
            }
            float r  = 1.f / (1.f + expf(-(x0 + s0)));
            float z  = 1.f / (1.f + expf(-(x1 + s1)));
            float n  = tanhf(x2 + r * s2);
            float hn = (1.f - z) * n + z * hprev;
            ys[((size_t)s * B_SZ + b0 + gb) * H_SZ + j0 + gj] = hn;
        }

        asm volatile("barrier.cluster.arrive.aligned;" ::: "memory");
        asm volatile("barrier.cluster.wait.aligned;"   ::: "memory");
    }
}

// ================= FALLBACK scan: exact round-6 kernel (cluster 8) =================
#define SCAN8_SMEM_BYTES ((4096 + 12288) * 4)

__global__ void __launch_bounds__(512, 1) __cluster_dims__(8, 1, 1)
scan8_kernel(const float* __restrict__ xg, const float4* __restrict__ wpk,
             float* __restrict__ ys, int S)
{
    extern __shared__ float sm[];
    float*  hs  = sm;
    float*  red = sm + 4096;
    float4* hs4 = (float4*)hs;

    const int tid  = threadIdx.x;
    const int lane = tid & 31;
    const int w    = tid >> 5;
    const int kc   = w >> 1;
    const int jh   = w & 1;
    const int j0   = blockIdx.x << 6;
    const int b0   = blockIdx.y << 3;
    const int col  = j0 + (jh << 5) + lane;
    const int k4b  = kc << 4;
    const int jc   = (jh << 5) + lane;

    const int gb = tid >> 6;
    const int gj = tid & 63;

    const float4* w0p = wpk + ((size_t)(0 * 128 + k4b) << 9) + col;
    const float4* w1p = wpk + ((size_t)(1 * 128 + k4b) << 9) + col;
    const float4* w2p = wpk + ((size_t)(2 * 128 + k4b) << 9) + col;

    for (int s = 0; s < S; s++) {
        if (s == 0) {
            for (int i = tid; i < 1024; i += 512) hs4[i] = make_float4(0.f, 0.f, 0.f, 0.f);
        } else {
            const float4* hp = (const float4*)(ys + ((size_t)(s - 1) * B_SZ + b0) * H_SZ);
            for (int i = tid; i < 1024; i += 512) hs4[i] = __ldcg(hp + i);
        }
        __syncthreads();

        float acc[3][8];
#pragma unroll
        for (int g = 0; g < 3; g++)
#pragma unroll
            for (int b = 0; b < 8; b++) acc[g][b] = 0.f;

#pragma unroll 4
        for (int t = 0; t < 16; t++) {
            float4 w0 = __ldg(w0p + ((size_t)t << 9));
            float4 w1 = __ldg(w1p + ((size_t)t << 9));
            float4 w2 = __ldg(w2p + ((size_t)t << 9));
            const int k4 = k4b + t;
#pragma unroll
            for (int b = 0; b < 8; b++) {
                float4 h4 = hs4[b * 128 + k4];
                acc[0][b] += h4.x * w0.x + h4.y * w0.y + h4.z * w0.z + h4.w * w0.w;
                acc[1][b] += h4.x * w1.x + h4.y * w1.y + h4.z * w1.z + h4.w * w1.w;
                acc[2][b] += h4.x * w2.x + h4.y * w2.y + h4.z * w2.z + h4.w * w2.w;
            }
        }

#pragma unroll
        for (int g = 0; g < 3; g++)
#pragma unroll
            for (int b = 0; b < 8; b++)
                red[((kc * 3 + g) * 8 + b) * 64 + jc] = acc[g][b];
        __syncthreads();

        float a0 = 0.f, a1 = 0.f, a2 = 0.f;
#pragma unroll
        for (int c = 0; c < 8; c++) {
            a0 += red[((c * 3 + 0) * 8 + gb) * 64 + gj];
            a1 += red[((c * 3 + 1) * 8 + gb) * 64 + gj];
            a2 += red[((c * 3 + 2) * 8 + gb) * 64 + gj];
        }

        float hprev = hs[gb * 512 + j0 + gj];

        const size_t xi = ((size_t)s * 3 * B_SZ + (b0 + gb)) * H_SZ + j0 + gj;
        float x0 = xg[xi];
        float x1 = xg[xi + (size_t)B_SZ * H_SZ];
        float x2 = xg[xi + (size_t)2 * B_SZ * H_SZ];

        float r  = 1.f / (1.f + expf(-(x0 + a0)));
        float z  = 1.f / (1.f + expf(-(x1 + a1)));
        float n  = tanhf(x2 + r * a2);
        float hn = (1.f - z) * n + z * hprev;

        ys[((size_t)s * B_SZ + b0 + gb) * H_SZ + j0 + gj] = hn;

        asm volatile("barrier.cluster.arrive.aligned;" ::: "memory");
        asm volatile("barrier.cluster.wait.aligned;"   ::: "memory");
    }
}

// ---------------- backward shortcut + final FC (unchanged) ----------------
__global__ void __launch_bounds__(128) bwd_step(
    const float* __restrict__ xin, long bstride, long off,
    const float* __restrict__ Wi, const float* __restrict__ bias,
    float* __restrict__ hout)
{
    int h = blockIdx.x * 128 + threadIdx.x;
    int b = blockIdx.y;
    const float* xr = xin + (size_t)b * bstride + off;
    const float* W1 = Wi + (size_t)1 * 512 * 512 + h;
    const float* W2 = Wi + (size_t)2 * 512 * 512 + h;
    float a1 = 0.f, a2 = 0.f;
    for (int k = 0; k < 512; k++) {
        float xv = __ldg(xr + k);
        a1 += xv * W1[(size_t)k * 512];
        a2 += xv * W2[(size_t)k * 512];
    }
    float z = 1.f / (1.f + expf(-(a1 + bias[512 + h])));
    float n = tanhf(a2 + bias[1024 + h]);
    hout[(size_t)b * 512 + h] = (1.f - z) * n;
}

__global__ void __launch_bounds__(128) fc_kernel(
    const float* __restrict__ ysl, const float* __restrict__ hb,
    const float* __restrict__ fw, const float* __restrict__ fb,
    float* __restrict__ out)
{
    int o = blockIdx.x * 128 + threadIdx.x;
    int b = blockIdx.y;
    float acc = fb[o];
    const float* f0 = ysl + (size_t)b * 512;
    const float* h0 = hb  + (size_t)b * 512;
    for (int jq = 0; jq < 512; jq++) acc += f0[jq] * fw[(size_t)jq * 512 + o];
    for (int jq = 0; jq < 512; jq++) acc += h0[jq] * fw[(size_t)(512 + jq) * 512 + o];
    out[(size_t)b * 512 + o] = acc;
}

// ---------------- launch ----------------
extern "C" void kernel_launch(void* const* d_in, const int* in_sizes, int n_in,
                              void* d_out, int out_size)
{
    (void)in_sizes; (void)n_in; (void)out_size;
    const float* x  = (const float*)d_in[0];
    const float* Wi = (const float*)d_in[1];
    const float* Wh = (const float*)d_in[2];
    const float* bb = (const float*)d_in[3];
    const float* fw = (const float*)d_in[4];
    const float* fb = (const float*)d_in[5];
    float* out = (float*)d_out;

    float *xg, *ys0, *ys1, *hb0, *hb1, *wpk0, *wpk1, *wf0, *wf1;
    cudaGetSymbolAddress((void**)&xg,   g_xg);
    cudaGetSymbolAddress((void**)&ys0,  g_ys0);
    cudaGetSymbolAddress((void**)&ys1,  g_ys1);
    cudaGetSymbolAddress((void**)&hb0,  g_hb0);
    cudaGetSymbolAddress((void**)&hb1,  g_hb1);
    cudaGetSymbolAddress((void**)&wpk0, g_wpk0);
    cudaGetSymbolAddress((void**)&wpk1, g_wpk1);
    cudaGetSymbolAddress((void**)&wf0,  g_wf0);
    cudaGetSymbolAddress((void**)&wf1,  g_wf1);

    cudaFuncSetAttribute(scan16t_kernel, cudaFuncAttributeMaxDynamicSharedMemorySize,
                         S16T_SMEM_BYTES);
    cudaFuncSetAttribute(scan16t_kernel, cudaFuncAttributeNonPortableClusterSizeAllowed, 1);
    cudaFuncSetAttribute(scan8_kernel, cudaFuncAttributeMaxDynamicSharedMemorySize,
                         SCAN8_SMEM_BYTES);

    int maxc = 0;
    {
        cudaLaunchConfig_t qcfg = {};
        qcfg.gridDim = dim3(16, 4);
        qcfg.blockDim = dim3(512);
        qcfg.dynamicSmemBytes = S16T_SMEM_BYTES;
        if (cudaOccupancyMaxPotentialClusterSize(&maxc, scan16t_kernel, &qcfg) != cudaSuccess)
            maxc = 0;
    }
    const bool use16 = (maxc >= 16);

    const size_t WSLAB = (size_t)3 * 512 * 512;
    const size_t BSLAB = (size_t)3 * 512;
    const size_t YSSTEP = (size_t)B_SZ * H_SZ;

    dim3 pgrid(12, 512);
    int  pkblocks = (3 * 512 * 512 + 255) / 256;

    if (use16) {
        pack_frag<<<(FRAG_PAIRS + 255) / 256, 256>>>(Wh + 0 * WSLAB, wf0);
        pack_frag<<<(FRAG_PAIRS + 255) / 256, 256>>>(Wh + 2 * WSLAB, wf1);
    } else {
        pack_wh<<<pkblocks, 256>>>(Wh + 0 * WSLAB, wpk0);
        pack_wh<<<pkblocks, 256>>>(Wh + 2 * WSLAB, wpk1);
    }

    auto launch_scan = [&](const float* xgp, const float* wfp, const float* wpkp, float* ysp) {
        if (use16) {
            cudaLaunchConfig_t cfg = {};
            cfg.gridDim = dim3(16, 4);
            cfg.blockDim = dim3(512);
            cfg.dynamicSmemBytes = S16T_SMEM_BYTES;
            cfg.stream = 0;
            cudaLaunchAttribute at[1];
            at[0].id = cudaLaunchAttributeClusterDimension;
            at[0].val.clusterDim.x = 16;
            at[0].val.clusterDim.y = 1;
            at[0].val.clusterDim.z = 1;
            cfg.attrs = at;
            cfg.numAttrs = 1;
            int S = S_SZ;
            cudaLaunchKernelEx(&cfg, scan16t_kernel, xgp, wfp, ysp, S);
        } else {
            scan8_kernel<<<dim3(8, 8), 512, SCAN8_SMEM_BYTES>>>(
                xgp, (const float4*)wpkp, ysp, S_SZ);
        }
    };

    proj_kernel<<<pgrid, 256>>>(x, (long)S_SZ * I_SZ, (long)I_SZ,
                                Wi + 0 * WSLAB, bb + 0 * BSLAB, xg, S_SZ);
    launch_scan(xg, wf0, wpk0, ys0);

    proj_kernel<<<pgrid, 256>>>(ys0, (long)H_SZ, (long)B_SZ * H_SZ,
                                Wi + 2 * WSLAB, bb + 2 * BSLAB, xg, S_SZ);
    launch_scan(xg, wf1, wpk1, ys1);

    dim3 bgrid(4, 64);
    bwd_step<<<bgrid, 128>>>(x, (long)S_SZ * I_SZ, (long)(S_SZ - 1) * I_SZ,
                             Wi + 1 * WSLAB, bb + 1 * BSLAB, hb0);
    bwd_step<<<bgrid, 128>>>(hb0, (long)H_SZ, 0L,
                             Wi + 3 * WSLAB, bb + 3 * BSLAB, hb1);

    fc_kernel<<<bgrid, 128>>>(ys1 + (size_t)(S_SZ - 1) * YSSTEP, hb1, fw, fb, out);
}

// round 13
// speedup vs baseline: 2.3254x; 1.0295x over previous
#include <cuda_runtime.h>
#include <math.h>

#define B_SZ 64
#define S_SZ 1024
#define I_SZ 512
#define H_SZ 512

// ---------------- static device scratch (no allocations allowed) ----------------
__device__ float g_xg  [(size_t)S_SZ * 3 * B_SZ * H_SZ];  // [S][3][B][H]
__device__ float g_ys0 [(size_t)S_SZ * B_SZ * H_SZ];      // layer-0 fwd outputs [S][B][H]
__device__ float g_ys1 [(size_t)S_SZ * B_SZ * H_SZ];      // layer-1 fwd outputs
__device__ float g_hb0 [B_SZ * H_SZ];
__device__ float g_hb1 [B_SZ * H_SZ];
__device__ float g_wpk0[3 * 512 * 512];                   // packed Wh layer0 (fallback path)
__device__ float g_wpk1[3 * 512 * 512];                   // packed Wh layer1 (fallback path)
__device__ float g_wf0 [3 * 512 * 512];                   // frag-packed Wh layer0 (tensor path)
__device__ float g_wf1 [3 * 512 * 512];                   // frag-packed Wh layer1 (tensor path)

// ---------------- tf32 helpers ----------------
__device__ __forceinline__ unsigned f2tf(float x) {
    unsigned u;
    asm("cvt.rna.tf32.f32 %0, %1;" : "=r"(u) : "f"(x));
    return u;
}

__device__ __forceinline__ void mma8(float* c, const unsigned* a, unsigned b0, unsigned b1) {
    asm volatile(
        "mma.sync.aligned.m16n8k8.row.col.f32.tf32.tf32.f32 "
        "{%0,%1,%2,%3}, {%4,%5,%6,%7}, {%8,%9}, {%0,%1,%2,%3};"
        : "+f"(c[0]), "+f"(c[1]), "+f"(c[2]), "+f"(c[3])
        : "r"(a[0]), "r"(a[1]), "r"(a[2]), "r"(a[3]), "r"(b0), "r"(b1));
}

// ---------------- projection GEMM (round-12 verified; K-loop software-pipelined) ----------------
__global__ void __launch_bounds__(256) proj_kernel(
    const float* __restrict__ X, long sb, long ss,
    const float* __restrict__ W, const float* __restrict__ bias,
    float* __restrict__ out, int Srows)
{
    __shared__ float As[128][36];
    __shared__ float Bs[32][136];

    const int M  = Srows * B_SZ;
    const int m0 = blockIdx.y * 128;
    const int n0 = blockIdx.x * 128;
    const int g  = n0 >> 9;
    const int h0 = n0 & 511;
    const float* Wg = W + (size_t)g * H_SZ * H_SZ;

    const int tid  = threadIdx.x;
    const int lane = tid & 31;
    const int warp = tid >> 5;
    const int wm   = warp & 3;
    const int wn   = warp >> 2;

    float acc[2][8][4];
#pragma unroll
    for (int i = 0; i < 2; i++)
#pragma unroll
        for (int jf = 0; jf < 8; jf++)
#pragma unroll
            for (int k = 0; k < 4; k++) acc[i][jf][k] = 0.f;

    // staged-tile registers
    float4 av[4], bv[4];

    // prologue: fetch k0 = 0
#pragma unroll
    for (int i = 0; i < 4; i++) {
        int idx = tid + i * 256;
        int row = idx >> 3;
        int kk  = (idx & 7) << 2;
        av[i] = make_float4(0.f, 0.f, 0.f, 0.f);
        int r = m0 + row;
        if (r < M) {
            int s = r >> 6, b = r & 63;
            av[i] = *(const float4*)(X + (size_t)b * sb + (size_t)s * ss + kk);
        }
        int kkb = idx >> 5;
        int nn  = (idx & 31) << 2;
        bv[i] = *(const float4*)(Wg + (size_t)kkb * H_SZ + h0 + nn);
    }

    for (int k0 = 0; k0 < H_SZ; k0 += 32) {
        // store staged regs into smem (tf32-rounded)
#pragma unroll
        for (int i = 0; i < 4; i++) {
            int idx = tid + i * 256;
            int row = idx >> 3;
            int kk  = (idx & 7) << 2;
            As[row][kk + 0] = __uint_as_float(f2tf(av[i].x));
            As[row][kk + 1] = __uint_as_float(f2tf(av[i].y));
            As[row][kk + 2] = __uint_as_float(f2tf(av[i].z));
            As[row][kk + 3] = __uint_as_float(f2tf(av[i].w));
            int kkb = idx >> 5;
            int nn  = (idx & 31) << 2;
            Bs[kkb][nn + 0] = __uint_as_float(f2tf(bv[i].x));
            Bs[kkb][nn + 1] = __uint_as_float(f2tf(bv[i].y));
            Bs[kkb][nn + 2] = __uint_as_float(f2tf(bv[i].z));
            Bs[kkb][nn + 3] = __uint_as_float(f2tf(bv[i].w));
        }
        __syncthreads();

        // prefetch next K-tile (overlaps with compute below)
        if (k0 + 32 < H_SZ) {
            const int kn = k0 + 32;
#pragma unroll
            for (int i = 0; i < 4; i++) {
                int idx = tid + i * 256;
                int row = idx >> 3;
                int kk  = (idx & 7) << 2;
                av[i] = make_float4(0.f, 0.f, 0.f, 0.f);
                int r = m0 + row;
                if (r < M) {
                    int s = r >> 6, b = r & 63;
                    av[i] = *(const float4*)(X + (size_t)b * sb + (size_t)s * ss + kn + kk);
                }
                int kkb = idx >> 5;
                int nn  = (idx & 31) << 2;
                bv[i] = *(const float4*)(Wg + (size_t)(kn + kkb) * H_SZ + h0 + nn);
            }
        }

#pragma unroll
        for (int kq = 0; kq < 4; kq++) {
            const int kr = kq * 8;
            unsigned a[2][4];
#pragma unroll
            for (int mf = 0; mf < 2; mf++) {
                int rb = wm * 32 + mf * 16 + (lane >> 2);
                int c  = kr + (lane & 3);
                a[mf][0] = __float_as_uint(As[rb][c]);
                a[mf][1] = __float_as_uint(As[rb + 8][c]);
                a[mf][2] = __float_as_uint(As[rb][c + 4]);
                a[mf][3] = __float_as_uint(As[rb + 8][c + 4]);
            }
#pragma unroll
            for (int nf = 0; nf < 8; nf++) {
                int cb = wn * 64 + nf * 8 + (lane >> 2);
                unsigned b0 = __float_as_uint(Bs[kr + (lane & 3)][cb]);
                unsigned b1 = __float_as_uint(Bs[kr + (lane & 3) + 4][cb]);
                mma8(acc[0][nf], a[0], b0, b1);
                mma8(acc[1][nf], a[1], b0, b1);
            }
        }
        __syncthreads();
    }

#pragma unroll
    for (int mf = 0; mf < 2; mf++) {
#pragma unroll
        for (int nf = 0; nf < 8; nf++) {
            int col = wn * 64 + nf * 8 + ((lane & 3) << 1);
            int h   = h0 + col;
            float b0v = bias[g * H_SZ + h];
            float b1v = bias[g * H_SZ + h + 1];
            int r = m0 + wm * 32 + mf * 16 + (lane >> 2);
            if (r < M) {
                int s = r >> 6, b = r & 63;
                float* o = out + ((size_t)(s * 3 + g) * B_SZ + b) * H_SZ + h;
                o[0] = acc[mf][nf][0] + b0v;
                o[1] = acc[mf][nf][1] + b1v;
            }
            int r2 = r + 8;
            if (r2 < M) {
                int s = r2 >> 6, b = r2 & 63;
                float* o = out + ((size_t)(s * 3 + g) * B_SZ + b) * H_SZ + h;
                o[0] = acc[mf][nf][2] + b0v;
                o[1] = acc[mf][nf][3] + b1v;
            }
        }
    }
}

// ---------------- Wh pre-pack for fallback scan8 ----------------
__global__ void __launch_bounds__(256) pack_wh(const float* __restrict__ Wh,
                                               float* __restrict__ wpk)
{
    int idx = blockIdx.x * 256 + threadIdx.x;
    if (idx < 3 * 512 * 512) {
        int col = idx & 511;
        int k   = (idx >> 9) & 511;
        int g   = idx >> 18;
        wpk[((((size_t)g * 128 + (k >> 2)) * 512 + col) << 2) + (k & 3)] = Wh[idx];
    }
}

// ---------------- Wh frag-pack for tensor scan (verified round 11) ----------------
#define FRAG_PAIRS 393216
__global__ void __launch_bounds__(256) pack_frag(const float* __restrict__ Wh,
                                                 float* __restrict__ wf)
{
    int p = blockIdx.x * 256 + threadIdx.x;
    if (p < FRAG_PAIRS) {
        int lane = p & 31;
        int kt   = (p >> 5) & 63;
        int nf   = (p >> 11) & 3;
        int cg   = (p >> 13) & 15;
        int g    = p >> 17;
        int col  = cg * 32 + nf * 8 + (lane >> 2);
        int k    = kt * 8 + (lane & 3);
        wf[2 * p + 0] = __uint_as_float(f2tf(Wh[((size_t)g * 512 + k) * 512 + col]));
        wf[2 * p + 1] = __uint_as_float(f2tf(Wh[((size_t)g * 512 + k + 4) * 512 + col]));
    }
}

// ================= PRIMARY scan: tensor-core mma, cluster-16 (round-12 base) =================
// Changes vs round 12: hprev carried in register; split cluster barrier with xg
// prefetch in the arrive/wait gap; ys stores tf32-pre-rounded h so staging is a pure copy.
#define W2_KT    9
#define HS_STRIDE 516
#define SM_WSM   0
#define SM_W2    32768
#define SM_HSHI  (32768 + 4 * W2_KT * 4 * 32 * 2)     // 41984
#define SM_RED   (SM_HSHI + 16 * HS_STRIDE)           // 50240
#define S16T_SMEM_FLOATS (SM_RED + 4 * 16 * 100)      // 56640
#define S16T_SMEM_BYTES  (S16T_SMEM_FLOATS * 4)       // 226560 B

// MODE 0: weights fully in smem (gates 0,1). MODE 1: gate 2 mixed smem/L2.
template <int MODE>
__device__ __forceinline__ void matvec_part(
    const float* __restrict__ sm, const float* __restrict__ wsmg,
    const unsigned long long* __restrict__ w2sm,
    const unsigned long long* __restrict__ wfgkc,
    int ktb, int lane, float c[4][4])
{
    const int rb  = lane >> 2;
    const int kap = lane & 3;
#pragma unroll 4
    for (int kt = 0; kt < 16; kt++) {
        const int k0 = (ktb + kt) << 3;
        const int ab = rb * HS_STRIDE + k0 + kap;
        unsigned ah[4];
        ah[0] = __float_as_uint(sm[SM_HSHI + ab]);
        ah[1] = __float_as_uint(sm[SM_HSHI + ab + 8 * HS_STRIDE]);
        ah[2] = __float_as_uint(sm[SM_HSHI + ab + 4]);
        ah[3] = __float_as_uint(sm[SM_HSHI + ab + 8 * HS_STRIDE + 4]);
#pragma unroll
        for (int nf = 0; nf < 4; nf++) {
            unsigned long long bv;
            if (MODE == 0)
                bv = *(const unsigned long long*)(wsmg + nf * 4096 + (ktb + kt) * 64 + lane * 2);
            else if (kt < W2_KT)
                bv = w2sm[(kt * 4 + nf) * 32];
            else
                bv = __ldg(wfgkc + nf * 2048 + kt * 32);
            mma8(c[nf], ah, (unsigned)bv, (unsigned)(bv >> 32));
        }
    }
}

__global__ void __launch_bounds__(512, 1)
scan16t_kernel(const float* __restrict__ xg,   // [S][3][B][H]
               const float* __restrict__ wf,   // frag-packed Wh (this layer)
               float* __restrict__ ys,         // [S][B][H] (stores tf32-rounded h)
               int S)
{
    extern __shared__ float sm[];

    const int tid  = threadIdx.x;
    const int lane = tid & 31;
    const int w    = tid >> 5;
    const int kc   = w & 3;
    const int g    = w >> 2;
    const int cg   = blockIdx.x;
    const int j0   = cg << 5;
    const int b0   = blockIdx.y << 4;

    // one-time: gates 0,1 frag slices into smem
    {
        const float4* src = (const float4*)(wf);
        float4*       dst = (float4*)(sm + SM_WSM);
#pragma unroll
        for (int gg = 0; gg < 2; gg++) {
            const float4* s4 = src + (size_t)(gg * 16 + cg) * 4096;
            float4*       d4 = dst + gg * 4096;
            for (int i = tid; i < 4096; i += 512) d4[i] = s4[i];
        }
    }

    const unsigned long long* wfg =
        (const unsigned long long*)wf + ((size_t)(2 * 16 + cg) * 4) * 2048;

    // one-time: gate-2 partial cache: [kc][t<W2_KT][nf][lane]
    {
        unsigned long long* w2 = (unsigned long long*)(sm + SM_W2);
        for (int i = tid; i < 4 * W2_KT * 4 * 32; i += 512) {
            int ln = i & 31;
            int nf = (i >> 5) & 3;
            int r  = i >> 7;
            int kcc = r / W2_KT;
            int t   = r % W2_KT;
            w2[i] = wfg[nf * 2048 + (kcc * 16 + t) * 32 + ln];
        }
    }

    const float* wsmg = sm + SM_WSM + (g < 2 ? g * 16384 : 0);
    const unsigned long long* w2sm =
        (const unsigned long long*)(sm + SM_W2) + (kc * W2_KT * 4) * 32 + lane;
    const unsigned long long* wfgkc = wfg + (kc * 16) * 32 + lane;

    const int gb = tid >> 5;   // gate-stage batch (0..15)
    const int gj = tid & 31;   // gate-stage col   (0..31)

    // register-carried recurrence state for this thread's (b0+gb, j0+gj)
    float hprev = 0.f;

    // prefetch xg for step 0
    float x0, x1, x2;
    {
        const size_t xb = ((size_t)(0 * 3 + 0) * B_SZ + b0 + gb) * H_SZ + j0 + gj;
        x0 = __ldg(xg + xb);
        x1 = __ldg(xg + xb + (size_t)B_SZ * H_SZ);
        x2 = __ldg(xg + xb + (size_t)2 * B_SZ * H_SZ);
    }

    for (int s = 0; s < S; s++) {
        // stage h_prev [16][512]: ys already holds tf32-rounded values -> pure copy
        if (s == 0) {
            float4 z = make_float4(0.f, 0.f, 0.f, 0.f);
            for (int i = tid; i < 16 * 129; i += 512)
                ((float4*)(sm + SM_HSHI))[i] = z;
        } else {
#pragma unroll
            for (int it = 0; it < 4; it++) {
                int i  = tid + it * 512;
                int b  = i >> 7;
                int k4 = i & 127;
                float4 v = __ldcg((const float4*)(ys + ((size_t)(s - 1) * B_SZ + b0 + b) * H_SZ) + k4);
                *(float4*)&sm[SM_HSHI + b * HS_STRIDE + (k4 << 2)] = v;
            }
        }
        __syncthreads();

        // tensor matvec (warps 0-11)
        if (w < 12) {
            float c[4][4];
#pragma unroll
            for (int nf = 0; nf < 4; nf++)
#pragma unroll
                for (int q = 0; q < 4; q++) c[nf][q] = 0.f;

            if (g < 2) matvec_part<0>(sm, wsmg, w2sm, wfgkc, kc * 16, lane, c);
            else       matvec_part<1>(sm, wsmg, w2sm, wfgkc, kc * 16, lane, c);

#pragma unroll
            for (int nf = 0; nf < 4; nf++) {
                int gcol = (g << 5) + (nf << 3) + ((lane & 3) << 1);
                int row  = lane >> 2;
                float2 p01 = make_float2(c[nf][0], c[nf][1]);
                float2 p23 = make_float2(c[nf][2], c[nf][3]);
                *(float2*)&sm[SM_RED + kc * 1600 + row * 100 + gcol]       = p01;
                *(float2*)&sm[SM_RED + kc * 1600 + (row + 8) * 100 + gcol] = p23;
            }
        }
        __syncthreads();

        // gate stage: 512 threads, one per (batch gb, col gj)
        {
            float s0 = 0.f, s1 = 0.f, s2 = 0.f;
#pragma unroll
            for (int c8 = 0; c8 < 4; c8++) {
                s0 += sm[SM_RED + c8 * 1600 + gb * 100 +      gj];
                s1 += sm[SM_RED + c8 * 1600 + gb * 100 + 32 + gj];
                s2 += sm[SM_RED + c8 * 1600 + gb * 100 + 64 + gj];
            }
            float r  = 1.f / (1.f + expf(-(x0 + s0)));
            float z  = 1.f / (1.f + expf(-(x1 + s1)));
            float n  = tanhf(x2 + r * s2);
            float hn = (1.f - z) * n + z * hprev;
            hprev = hn;   // exact state carried in register
            // store tf32-pre-rounded (what the mma consumes anyway)
            ys[((size_t)s * B_SZ + b0 + gb) * H_SZ + j0 + gj] = __uint_as_float(f2tf(hn));
        }

        // split cluster barrier; prefetch next xg in the gap
        asm volatile("barrier.cluster.arrive.aligned;" ::: "memory");
        if (s + 1 < S) {
            const size_t xb = ((size_t)((s + 1) * 3 + 0) * B_SZ + b0 + gb) * H_SZ + j0 + gj;
            x0 = __ldg(xg + xb);
            x1 = __ldg(xg + xb + (size_t)B_SZ * H_SZ);
            x2 = __ldg(xg + xb + (size_t)2 * B_SZ * H_SZ);
        }
        asm volatile("barrier.cluster.wait.aligned;" ::: "memory");
    }
}

// ================= FALLBACK scan: exact round-6 kernel (cluster 8) =================
#define SCAN8_SMEM_BYTES ((4096 + 12288) * 4)

__global__ void __launch_bounds__(512, 1) __cluster_dims__(8, 1, 1)
scan8_kernel(const float* __restrict__ xg, const float4* __restrict__ wpk,
             float* __restrict__ ys, int S)
{
    extern __shared__ float sm[];
    float*  hs  = sm;
    float*  red = sm + 4096;
    float4* hs4 = (float4*)hs;

    const int tid  = threadIdx.x;
    const int lane = tid & 31;
    const int w    = tid >> 5;
    const int kc   = w >> 1;
    const int jh   = w & 1;
    const int j0   = blockIdx.x << 6;
    const int b0   = blockIdx.y << 3;
    const int col  = j0 + (jh << 5) + lane;
    const int k4b  = kc << 4;
    const int jc   = (jh << 5) + lane;

    const int gb = tid >> 6;
    const int gj = tid & 63;

    const float4* w0p = wpk + ((size_t)(0 * 128 + k4b) << 9) + col;
    const float4* w1p = wpk + ((size_t)(1 * 128 + k4b) << 9) + col;
    const float4* w2p = wpk + ((size_t)(2 * 128 + k4b) << 9) + col;

    for (int s = 0; s < S; s++) {
        if (s == 0) {
            for (int i = tid; i < 1024; i += 512) hs4[i] = make_float4(0.f, 0.f, 0.f, 0.f);
        } else {
            const float4* hp = (const float4*)(ys + ((size_t)(s - 1) * B_SZ + b0) * H_SZ);
            for (int i = tid; i < 1024; i += 512) hs4[i] = __ldcg(hp + i);
        }
        __syncthreads();

        float acc[3][8];
#pragma unroll
        for (int g = 0; g < 3; g++)
#pragma unroll
            for (int b = 0; b < 8; b++) acc[g][b] = 0.f;

#pragma unroll 4
        for (int t = 0; t < 16; t++) {
            float4 w0 = __ldg(w0p + ((size_t)t << 9));
            float4 w1 = __ldg(w1p + ((size_t)t << 9));
            float4 w2 = __ldg(w2p + ((size_t)t << 9));
            const int k4 = k4b + t;
#pragma unroll
            for (int b = 0; b < 8; b++) {
                float4 h4 = hs4[b * 128 + k4];
                acc[0][b] += h4.x * w0.x + h4.y * w0.y + h4.z * w0.z + h4.w * w0.w;
                acc[1][b] += h4.x * w1.x + h4.y * w1.y + h4.z * w1.z + h4.w * w1.w;
                acc[2][b] += h4.x * w2.x + h4.y * w2.y + h4.z * w2.z + h4.w * w2.w;
            }
        }

#pragma unroll
        for (int g = 0; g < 3; g++)
#pragma unroll
            for (int b = 0; b < 8; b++)
                red[((kc * 3 + g) * 8 + b) * 64 + jc] = acc[g][b];
        __syncthreads();

        float a0 = 0.f, a1 = 0.f, a2 = 0.f;
#pragma unroll
        for (int c = 0; c < 8; c++) {
            a0 += red[((c * 3 + 0) * 8 + gb) * 64 + gj];
            a1 += red[((c * 3 + 1) * 8 + gb) * 64 + gj];
            a2 += red[((c * 3 + 2) * 8 + gb) * 64 + gj];
        }

        float hprev = hs[gb * 512 + j0 + gj];

        const size_t xi = ((size_t)s * 3 * B_SZ + (b0 + gb)) * H_SZ + j0 + gj;
        float x0 = xg[xi];
        float x1 = xg[xi + (size_t)B_SZ * H_SZ];
        float x2 = xg[xi + (size_t)2 * B_SZ * H_SZ];

        float r  = 1.f / (1.f + expf(-(x0 + a0)));
        float z  = 1.f / (1.f + expf(-(x1 + a1)));
        float n  = tanhf(x2 + r * a2);
        float hn = (1.f - z) * n + z * hprev;

        ys[((size_t)s * B_SZ + b0 + gb) * H_SZ + j0 + gj] = hn;

        asm volatile("barrier.cluster.arrive.aligned;" ::: "memory");
        asm volatile("barrier.cluster.wait.aligned;"   ::: "memory");
    }
}

// ---------------- backward shortcut + final FC (unchanged) ----------------
__global__ void __launch_bounds__(128) bwd_step(
    const float* __restrict__ xin, long bstride, long off,
    const float* __restrict__ Wi, const float* __restrict__ bias,
    float* __restrict__ hout)
{
    int h = blockIdx.x * 128 + threadIdx.x;
    int b = blockIdx.y;
    const float* xr = xin + (size_t)b * bstride + off;
    const float* W1 = Wi + (size_t)1 * 512 * 512 + h;
    const float* W2 = Wi + (size_t)2 * 512 * 512 + h;
    float a1 = 0.f, a2 = 0.f;
    for (int k = 0; k < 512; k++) {
        float xv = __ldg(xr + k);
        a1 += xv * W1[(size_t)k * 512];
        a2 += xv * W2[(size_t)k * 512];
    }
    float z = 1.f / (1.f + expf(-(a1 + bias[512 + h])));
    float n = tanhf(a2 + bias[1024 + h]);
    hout[(size_t)b * 512 + h] = (1.f - z) * n;
}

__global__ void __launch_bounds__(128) fc_kernel(
    const float* __restrict__ ysl, const float* __restrict__ hb,
    const float* __restrict__ fw, const float* __restrict__ fb,
    float* __restrict__ out)
{
    int o = blockIdx.x * 128 + threadIdx.x;
    int b = blockIdx.y;
    float acc = fb[o];
    const float* f0 = ysl + (size_t)b * 512;
    const float* h0 = hb  + (size_t)b * 512;
    for (int jq = 0; jq < 512; jq++) acc += f0[jq] * fw[(size_t)jq * 512 + o];
    for (int jq = 0; jq < 512; jq++) acc += h0[jq] * fw[(size_t)(512 + jq) * 512 + o];
    out[(size_t)b * 512 + o] = acc;
}

// ---------------- launch ----------------
extern "C" void kernel_launch(void* const* d_in, const int* in_sizes, int n_in,
                              void* d_out, int out_size)
{
    (void)in_sizes; (void)n_in; (void)out_size;
    const float* x  = (const float*)d_in[0];
    const float* Wi = (const float*)d_in[1];
    const float* Wh = (const float*)d_in[2];
    const float* bb = (const float*)d_in[3];
    const float* fw = (const float*)d_in[4];
    const float* fb = (const float*)d_in[5];
    float* out = (float*)d_out;

    float *xg, *ys0, *ys1, *hb0, *hb1, *wpk0, *wpk1, *wf0, *wf1;
    cudaGetSymbolAddress((void**)&xg,   g_xg);
    cudaGetSymbolAddress((void**)&ys0,  g_ys0);
    cudaGetSymbolAddress((void**)&ys1,  g_ys1);
    cudaGetSymbolAddress((void**)&hb0,  g_hb0);
    cudaGetSymbolAddress((void**)&hb1,  g_hb1);
    cudaGetSymbolAddress((void**)&wpk0, g_wpk0);
    cudaGetSymbolAddress((void**)&wpk1, g_wpk1);
    cudaGetSymbolAddress((void**)&wf0,  g_wf0);
    cudaGetSymbolAddress((void**)&wf1,  g_wf1);

    cudaFuncSetAttribute(scan16t_kernel, cudaFuncAttributeMaxDynamicSharedMemorySize,
                         S16T_SMEM_BYTES);
    cudaFuncSetAttribute(scan16t_kernel, cudaFuncAttributeNonPortableClusterSizeAllowed, 1);
    cudaFuncSetAttribute(scan8_kernel, cudaFuncAttributeMaxDynamicSharedMemorySize,
                         SCAN8_SMEM_BYTES);

    int maxc = 0;
    {
        cudaLaunchConfig_t qcfg = {};
        qcfg.gridDim = dim3(16, 4);
        qcfg.blockDim = dim3(512);
        qcfg.dynamicSmemBytes = S16T_SMEM_BYTES;
        if (cudaOccupancyMaxPotentialClusterSize(&maxc, scan16t_kernel, &qcfg) != cudaSuccess)
            maxc = 0;
    }
    const bool use16 = (maxc >= 16);

    const size_t WSLAB = (size_t)3 * 512 * 512;
    const size_t BSLAB = (size_t)3 * 512;
    const size_t YSSTEP = (size_t)B_SZ * H_SZ;

    dim3 pgrid(12, 512);
    int  pkblocks = (3 * 512 * 512 + 255) / 256;

    if (use16) {
        pack_frag<<<(FRAG_PAIRS + 255) / 256, 256>>>(Wh + 0 * WSLAB, wf0);
        pack_frag<<<(FRAG_PAIRS + 255) / 256, 256>>>(Wh + 2 * WSLAB, wf1);
    } else {
        pack_wh<<<pkblocks, 256>>>(Wh + 0 * WSLAB, wpk0);
        pack_wh<<<pkblocks, 256>>>(Wh + 2 * WSLAB, wpk1);
    }

    auto launch_scan = [&](const float* xgp, const float* wfp, const float* wpkp, float* ysp) {
        if (use16) {
            cudaLaunchConfig_t cfg = {};
            cfg.gridDim = dim3(16, 4);
            cfg.blockDim = dim3(512);
            cfg.dynamicSmemBytes = S16T_SMEM_BYTES;
            cfg.stream = 0;
            cudaLaunchAttribute at[1];
            at[0].id = cudaLaunchAttributeClusterDimension;
            at[0].val.clusterDim.x = 16;
            at[0].val.clusterDim.y = 1;
            at[0].val.clusterDim.z = 1;
            cfg.attrs = at;
            cfg.numAttrs = 1;
            int S = S_SZ;
            cudaLaunchKernelEx(&cfg, scan16t_kernel, xgp, wfp, ysp, S);
        } else {
            scan8_kernel<<<dim3(8, 8), 512, SCAN8_SMEM_BYTES>>>(
                xgp, (const float4*)wpkp, ysp, S_SZ);
        }
    };

    proj_kernel<<<pgrid, 256>>>(x, (long)S_SZ * I_SZ, (long)I_SZ,
                                Wi + 0 * WSLAB, bb + 0 * BSLAB, xg, S_SZ);
    launch_scan(xg, wf0, wpk0, ys0);

    proj_kernel<<<pgrid, 256>>>(ys0, (long)H_SZ, (long)B_SZ * H_SZ,
                                Wi + 2 * WSLAB, bb + 2 * BSLAB, xg, S_SZ);
    launch_scan(xg, wf1, wpk1, ys1);

    dim3 bgrid(4, 64);
    bwd_step<<<bgrid, 128>>>(x, (long)S_SZ * I_SZ, (long)(S_SZ - 1) * I_SZ,
                             Wi + 1 * WSLAB, bb + 1 * BSLAB, hb0);
    bwd_step<<<bgrid, 128>>>(hb0, (long)H_SZ, 0L,
                             Wi + 3 * WSLAB, bb + 3 * BSLAB, hb1);

    fc_kernel<<<bgrid, 128>>>(ys1 + (size_t)(S_SZ - 1) * YSSTEP, hb1, fw, fb, out);
}